// round 8
// baseline (speedup 1.0000x reference)
#include <cuda_runtime.h>
#include <cuda_fp16.h>
#include <cstdint>
#include <math.h>

// Problem constants
#define SEQ    2048
#define BATCH  2
#define WIDTH  1024
#define NH     16
#define HD     64
#define WIN    256
#define TOK    (BATCH*SEQ)     // 4096
#define NQKV   1152            // 1024 q + 64 k + 64 v

#define MASKVAL (-3.0e38f)

// ---------------------------------------------------------------------------
// Scratch (device globals).  fp16 split: activations hi+lo, weights hi only.
// ---------------------------------------------------------------------------
__device__ __half g_Ah[TOK * WIDTH],  g_Al[TOK * WIDTH];    // x hi/lo
__device__ __half g_Wh[NQKV * WIDTH];                        // [Wq;Wk;Wv] hi
__device__ __half g_Fh[WIDTH * WIDTH];                       // Wf hi
__device__ __half g_Qh[TOK * NQKV],  g_Ql[TOK * NQKV];       // qkv hi/lo
__device__ __half g_Oh[TOK * WIDTH], g_Ol[TOK * WIDTH];      // attn out hi/lo

// ---------------------------------------------------------------------------
// Helpers
// ---------------------------------------------------------------------------
__device__ __forceinline__ uint32_t smem_u32(const void* p) {
    uint32_t a;
    asm("{ .reg .u64 t; cvta.to.shared.u64 t, %1; cvt.u32.u64 %0, t; }"
        : "=r"(a) : "l"(p));
    return a;
}

#define CP_ASYNC16(sa, ga) \
    asm volatile("cp.async.cg.shared.global [%0], [%1], 16;" :: "r"(sa), "l"(ga))
#define CP_COMMIT() asm volatile("cp.async.commit_group;" ::: "memory")
#define CP_WAIT2()  asm volatile("cp.async.wait_group 2;" ::: "memory")
#define CP_WAIT1()  asm volatile("cp.async.wait_group 1;" ::: "memory")
#define CP_WAIT0()  asm volatile("cp.async.wait_group 0;" ::: "memory")

#define LDSM_X4(r0, r1, r2, r3, addr) \
    asm volatile("ldmatrix.sync.aligned.m8n8.x4.shared.b16 {%0,%1,%2,%3}, [%4];" \
        : "=r"(r0), "=r"(r1), "=r"(r2), "=r"(r3) : "r"(addr))
#define LDSM_X4T(r0, r1, r2, r3, addr) \
    asm volatile("ldmatrix.sync.aligned.m8n8.x4.trans.shared.b16 {%0,%1,%2,%3}, [%4];" \
        : "=r"(r0), "=r"(r1), "=r"(r2), "=r"(r3) : "r"(addr))

__device__ __forceinline__ void mma16816(float* c, const uint32_t* a,
                                         uint32_t b0, uint32_t b1) {
    asm volatile(
        "mma.sync.aligned.m16n8k16.row.col.f32.f16.f16.f32 "
        "{%0,%1,%2,%3}, {%4,%5,%6,%7}, {%8,%9}, {%0,%1,%2,%3};"
        : "+f"(c[0]), "+f"(c[1]), "+f"(c[2]), "+f"(c[3])
        : "r"(a[0]), "r"(a[1]), "r"(a[2]), "r"(a[3]), "r"(b0), "r"(b1));
}

__device__ __forceinline__ uint32_t packh(__half a, __half b) {
    __half2 t; t.x = a; t.y = b;
    return *(uint32_t*)&t;
}
__device__ __forceinline__ void split2h(float a, float b, uint32_t& hi, uint32_t& lo) {
    __half ah = __float2half_rn(a), bh = __float2half_rn(b);
    hi = packh(ah, bh);
    lo = packh(__float2half_rn(a - __half2float(ah)),
               __float2half_rn(b - __half2float(bh)));
}
__device__ __forceinline__ void split_h(float v, __half& h, __half& l) {
    h = __float2half_rn(v);
    l = __float2half_rn(v - __half2float(h));
}

// ---------------------------------------------------------------------------
// fp32 -> fp16 conversions
// ---------------------------------------------------------------------------
__global__ void convert_hl(const float* __restrict__ src,
                           __half* __restrict__ hi, __half* __restrict__ lo, int n) {
    int i = (blockIdx.x * blockDim.x + threadIdx.x) * 4;
    if (i >= n) return;
    float4 v = *(const float4*)(src + i);
    __half h0, h1, h2, h3, l0, l1, l2, l3;
    split_h(v.x, h0, l0); split_h(v.y, h1, l1);
    split_h(v.z, h2, l2); split_h(v.w, h3, l3);
    __half2* H = (__half2*)(hi + i);
    __half2* L = (__half2*)(lo + i);
    H[0] = __half2(h0, h1); H[1] = __half2(h2, h3);
    L[0] = __half2(l0, l1); L[1] = __half2(l2, l3);
}

__global__ void convert_h(const float* __restrict__ src,
                          __half* __restrict__ hi, int n) {
    int i = (blockIdx.x * blockDim.x + threadIdx.x) * 4;
    if (i >= n) return;
    float4 v = *(const float4*)(src + i);
    __half2* H = (__half2*)(hi + i);
    H[0] = __half2(__float2half_rn(v.x), __float2half_rn(v.y));
    H[1] = __half2(__float2half_rn(v.z), __float2half_rn(v.w));
}

__global__ void convert_w(const float* __restrict__ Wq, const float* __restrict__ Wk,
                          const float* __restrict__ Wv) {
    int row = blockIdx.x;
    const float* src;
    if (row < 1024)      src = Wq + (size_t)row * WIDTH;
    else if (row < 1088) src = Wk + (size_t)(row - 1024) * WIDTH;
    else                 src = Wv + (size_t)(row - 1088) * WIDTH;
    int c = threadIdx.x * 4;
    float4 v = *(const float4*)(src + c);
    __half2* H = (__half2*)(g_Wh + (size_t)row * WIDTH + c);
    H[0] = __half2(__float2half_rn(v.x), __float2half_rn(v.y));
    H[1] = __half2(__float2half_rn(v.z), __float2half_rn(v.w));
}

// ---------------------------------------------------------------------------
// mma.sync GEMM: C = A @ B^T (+bias).  A = Ah + Al (fp16 x2), B = Bh.
// 128x128x32 tile, 8 warps as 2(M)x4(N), 3-stage cp.async pipeline, 2 CTAs/SM.
// ---------------------------------------------------------------------------
#define BK 32
#define ROWB 80
#define ARR_B (128 * ROWB)            // 10240 B
#define STAGE_B (3 * ARR_B)           // Ah | Al | Bh = 30720 B
#define GEMM_SMEM (3 * STAGE_B)       // 92160 B -> 2 CTAs/SM

__global__ __launch_bounds__(256, 2)
void mmagemm(const __half* __restrict__ Ah, const __half* __restrict__ Al,
             const __half* __restrict__ Bh,
             float* __restrict__ C,
             __half* __restrict__ Ch, __half* __restrict__ Cl,
             int M, int N, int K, const float* __restrict__ bias) {
    extern __shared__ char smem[];
    uint32_t sb = smem_u32(smem);
    const int tid  = threadIdx.x;
    const int lane = tid & 31;
    const int wid  = tid >> 5;
    const int wm   = wid >> 2;        // 0..1  (M, 64 rows each)
    const int wn   = wid & 3;         // 0..3  (N, 32 cols each)
    const int m0 = blockIdx.y * 128;
    const int n0 = blockIdx.x * 128;
    const int NK = K / BK;
    const size_t RS = (size_t)K * 2;

    const int crow = tid >> 1;
    const int ccol = (tid & 1) * 2;
    const uint32_t s_off0 = crow * ROWB + ccol * 16;
    const char* gA0 = (const char*)Ah + (size_t)(m0 + crow) * RS + ccol * 16;
    const char* gA1 = (const char*)Al + (size_t)(m0 + crow) * RS + ccol * 16;
    const char* gB0 = (const char*)Bh + (size_t)(n0 + crow) * RS + ccol * 16;

    auto load_stage = [&](int s, int it) {
        uint32_t st = sb + s * STAGE_B;
        size_t kb = (size_t)it * (BK * 2);
        CP_ASYNC16(st + 0 * ARR_B + s_off0,      gA0 + kb);
        CP_ASYNC16(st + 0 * ARR_B + s_off0 + 16, gA0 + kb + 16);
        CP_ASYNC16(st + 1 * ARR_B + s_off0,      gA1 + kb);
        CP_ASYNC16(st + 1 * ARR_B + s_off0 + 16, gA1 + kb + 16);
        CP_ASYNC16(st + 2 * ARR_B + s_off0,      gB0 + kb);
        CP_ASYNC16(st + 2 * ARR_B + s_off0 + 16, gB0 + kb + 16);
    };

    float acc[4][4][4];
#pragma unroll
    for (int i = 0; i < 4; i++)
#pragma unroll
        for (int j = 0; j < 4; j++)
#pragma unroll
            for (int q = 0; q < 4; q++) acc[i][j][q] = 0.f;

    const int asub = lane >> 3;
    const int a_row_in = (lane & 7) + 8 * (asub & 1);
    const int a_chunk  = asub >> 1;
    const int b_row_in = (lane & 7) + 8 * (asub >> 1);
    const int b_chunk  = asub & 1;

    load_stage(0, 0); CP_COMMIT();
    load_stage(1, 1); CP_COMMIT();

    for (int it = 0; it < NK; ++it) {
        if (it + 2 < NK) { load_stage((it + 2) % 3, it + 2); CP_COMMIT(); CP_WAIT2(); }
        else if (it + 1 < NK) CP_WAIT1();
        else                  CP_WAIT0();
        __syncthreads();

        uint32_t st  = sb + (it % 3) * STAGE_B;
        uint32_t pAh = st;
        uint32_t pAl = st + ARR_B;
        uint32_t pBh = st + 2 * ARR_B;

#pragma unroll
        for (int kk = 0; kk < 2; kk++) {
            uint32_t ah[4][4], al[4][4], bh[2][4];
#pragma unroll
            for (int mt = 0; mt < 4; mt++) {
                uint32_t off = (uint32_t)((wm * 64 + mt * 16 + a_row_in) * ROWB +
                                          (kk * 2 + a_chunk) * 16);
                LDSM_X4(ah[mt][0], ah[mt][1], ah[mt][2], ah[mt][3], pAh + off);
                LDSM_X4(al[mt][0], al[mt][1], al[mt][2], al[mt][3], pAl + off);
            }
#pragma unroll
            for (int p = 0; p < 2; p++) {
                uint32_t off = (uint32_t)((wn * 32 + p * 16 + b_row_in) * ROWB +
                                          (kk * 2 + b_chunk) * 16);
                LDSM_X4(bh[p][0], bh[p][1], bh[p][2], bh[p][3], pBh + off);
            }
#pragma unroll
            for (int mt = 0; mt < 4; mt++)
#pragma unroll
                for (int p = 0; p < 2; p++)
#pragma unroll
                    for (int hh = 0; hh < 2; hh++) {
                        int nt = p * 2 + hh;
                        mma16816(acc[mt][nt], ah[mt], bh[p][hh * 2], bh[p][hh * 2 + 1]);
                        mma16816(acc[mt][nt], al[mt], bh[p][hh * 2], bh[p][hh * 2 + 1]);
                    }
        }
        __syncthreads();
    }

    const int gid = lane >> 2;
    const int qid = lane & 3;
#pragma unroll
    for (int mt = 0; mt < 4; mt++) {
        int r0 = m0 + wm * 64 + mt * 16 + gid;
#pragma unroll
        for (int nt = 0; nt < 4; nt++) {
            int c = n0 + wn * 32 + nt * 8 + qid * 2;
            if (C) {
                float b0 = 0.f, b1 = 0.f;
                if (bias) { b0 = bias[c]; b1 = bias[c + 1]; }
                *(float2*)&C[(size_t)r0 * N + c] =
                    make_float2(acc[mt][nt][0] + b0, acc[mt][nt][1] + b1);
                *(float2*)&C[(size_t)(r0 + 8) * N + c] =
                    make_float2(acc[mt][nt][2] + b0, acc[mt][nt][3] + b1);
            } else {
                uint32_t hi, lo;
                split2h(acc[mt][nt][0], acc[mt][nt][1], hi, lo);
                *(uint32_t*)&Ch[(size_t)r0 * N + c] = hi;
                *(uint32_t*)&Cl[(size_t)r0 * N + c] = lo;
                split2h(acc[mt][nt][2], acc[mt][nt][3], hi, lo);
                *(uint32_t*)&Ch[(size_t)(r0 + 8) * N + c] = hi;
                *(uint32_t*)&Cl[(size_t)(r0 + 8) * N + c] = lo;
            }
        }
    }
}

// ---------------------------------------------------------------------------
// Tensor-core windowed MQA flash attention, 128 q rows per CTA (256 thr,
// 8 warps x 16 rows).  S 3-product fp16; PV 2-product.  KV double-buffered.
// ---------------------------------------------------------------------------
#define AROWB 144
#define ATN_QARR  (128 * AROWB)       // 18432 B (Q hi or lo)
#define ATN_KARR  (64 * AROWB)        // 9216 B
#define ATN_SQH   0
#define ATN_SQL   ATN_QARR
#define ATN_STG   (2 * ATN_QARR)
#define ATN_STGSZ (3 * ATN_KARR)      // Kh | Kl | Vh
#define ATN_SMEM  (ATN_STG + 2 * ATN_STGSZ)   // 92160 B -> 2 CTAs/SM

__global__ __launch_bounds__(256, 2)
void attn_mma() {
    extern __shared__ char smc[];
    uint32_t sb = smem_u32(smc);
    const int qt = blockIdx.x, h = blockIdx.y, b = blockIdx.z;
    const int tid = threadIdx.x, lane = tid & 31, w = tid >> 5;
    const int g = lane >> 2, qd = lane & 3;
    const int r8 = lane & 7;

    // ---- async-load Q tile (128 rows, hi/lo) ----
    {
        const char* srcH = (const char*)g_Qh + (size_t)(b * SEQ + qt * 128) * 2304 + h * 128;
        const char* srcL = (const char*)g_Ql + (size_t)(b * SEQ + qt * 128) * 2304 + h * 128;
#pragma unroll
        for (int j = 0; j < 4; j++) {
            int lin = j * 256 + tid, row = lin >> 3, ch = lin & 7;
            CP_ASYNC16(sb + ATN_SQH + row * AROWB + ch * 16,
                       srcH + (size_t)row * 2304 + ch * 16);
            CP_ASYNC16(sb + ATN_SQL + row * AROWB + ch * 16,
                       srcL + (size_t)row * 2304 + ch * 16);
        }
    }

    auto load_kv = [&](int s, int kt) {
        size_t kb = (size_t)(b * SEQ + kt * 64) * 2304;
        uint32_t st = sb + ATN_STG + s * ATN_STGSZ;
#pragma unroll
        for (int j = 0; j < 6; j++) {
            int arr = j >> 1, lin = (j & 1) * 256 + tid;
            int row = lin >> 3, ch = lin & 7;
            const char* base = (arr == 0) ? (const char*)g_Qh + 2048
                             : (arr == 1) ? (const char*)g_Ql + 2048
                                          : (const char*)g_Qh + 2176;
            CP_ASYNC16(st + arr * ATN_KARR + row * AROWB + ch * 16,
                       base + kb + (size_t)row * 2304 + ch * 16);
        }
    };

    int ktlo = 2 * qt - 4; if (ktlo < 0) ktlo = 0;
    int kthi = 2 * qt + 5; if (kthi > SEQ / 64 - 1) kthi = SEQ / 64 - 1;

    load_kv(0, ktlo); CP_COMMIT();
    if (ktlo < kthi) { load_kv(1, ktlo + 1); CP_COMMIT(); }

    uint32_t qh[4][4], ql[4][4];
    float oacc[8][4];
#pragma unroll
    for (int i = 0; i < 8; i++)
#pragma unroll
        for (int j = 0; j < 4; j++) oacc[i][j] = 0.f;
    float m0 = -1e30f, m1 = -1e30f, l0 = 0.f, l1 = 0.f;

    const int qbase = qt * 128 + w * 16 + g;   // global q row for e<2 half

    for (int kt = ktlo; kt <= kthi; kt++) {
        int s = (kt - ktlo) & 1;
        if (kt < kthi) CP_WAIT1(); else CP_WAIT0();
        __syncthreads();

        if (kt == ktlo) {
#pragma unroll
            for (int ks = 0; ks < 4; ks++) {
                uint32_t off = (uint32_t)((w * 16 + (lane & 15)) * AROWB +
                                          ks * 32 + (lane >> 4) * 16);
                LDSM_X4(qh[ks][0], qh[ks][1], qh[ks][2], qh[ks][3], sb + ATN_SQH + off);
                LDSM_X4(ql[ks][0], ql[ks][1], ql[ks][2], ql[ks][3], sb + ATN_SQL + off);
            }
        }

        uint32_t stg = sb + ATN_STG + s * ATN_STGSZ;
        uint32_t pKh = stg, pKl = stg + ATN_KARR;
        uint32_t pVh = stg + 2 * ATN_KARR;

        // ---- S = Q @ K^T (3-product fp16) ----
        float sacc[8][4];
#pragma unroll
        for (int i = 0; i < 8; i++)
#pragma unroll
            for (int j = 0; j < 4; j++) sacc[i][j] = 0.f;

#pragma unroll
        for (int ks = 0; ks < 4; ks++)
#pragma unroll
            for (int sg = 0; sg < 4; sg++) {
                uint32_t off = (uint32_t)((sg * 16 + ((lane >> 4) & 1) * 8 + r8) * AROWB +
                                          ks * 32 + ((lane >> 3) & 1) * 16);
                uint32_t kh0, kh1, kh2, kh3, kl0, kl1, kl2, kl3;
                LDSM_X4(kh0, kh1, kh2, kh3, pKh + off);
                LDSM_X4(kl0, kl1, kl2, kl3, pKl + off);
                mma16816(sacc[sg * 2],     qh[ks], kh0, kh1);
                mma16816(sacc[sg * 2],     qh[ks], kl0, kl1);
                mma16816(sacc[sg * 2],     ql[ks], kh0, kh1);
                mma16816(sacc[sg * 2 + 1], qh[ks], kh2, kh3);
                mma16816(sacc[sg * 2 + 1], qh[ks], kl2, kl3);
                mma16816(sacc[sg * 2 + 1], ql[ks], kh2, kh3);
            }

        // ---- scale + (range-gated) window mask ----
#pragma unroll
        for (int nt = 0; nt < 8; nt++)
#pragma unroll
            for (int e = 0; e < 4; e++) sacc[nt][e] *= 0.125f;
        {
            int c = kt * 64 - qt * 128;
            if (c < -128 || c > 192) {
                int kbase = kt * 64 + 2 * qd;
#pragma unroll
                for (int nt = 0; nt < 8; nt++)
#pragma unroll
                    for (int e = 0; e < 4; e++) {
                        int ri = qbase + ((e >= 2) ? 8 : 0);
                        int cj = kbase + nt * 8 + (e & 1);
                        int d = ri - cj;
                        if (d > WIN || d < -WIN) sacc[nt][e] = MASKVAL;
                    }
            }
        }

        // ---- online softmax ----
        float rm0 = MASKVAL, rm1 = MASKVAL;
#pragma unroll
        for (int nt = 0; nt < 8; nt++) {
            rm0 = fmaxf(rm0, fmaxf(sacc[nt][0], sacc[nt][1]));
            rm1 = fmaxf(rm1, fmaxf(sacc[nt][2], sacc[nt][3]));
        }
        rm0 = fmaxf(rm0, __shfl_xor_sync(0xffffffffu, rm0, 1));
        rm0 = fmaxf(rm0, __shfl_xor_sync(0xffffffffu, rm0, 2));
        rm1 = fmaxf(rm1, __shfl_xor_sync(0xffffffffu, rm1, 1));
        rm1 = fmaxf(rm1, __shfl_xor_sync(0xffffffffu, rm1, 2));
        float nm0 = fmaxf(m0, rm0), nm1 = fmaxf(m1, rm1);
        float c0 = __expf(m0 - nm0), c1 = __expf(m1 - nm1);
        m0 = nm0; m1 = nm1;

        float sum0 = 0.f, sum1 = 0.f;
#pragma unroll
        for (int nt = 0; nt < 8; nt++) {
            sacc[nt][0] = __expf(sacc[nt][0] - nm0);
            sacc[nt][1] = __expf(sacc[nt][1] - nm0);
            sacc[nt][2] = __expf(sacc[nt][2] - nm1);
            sacc[nt][3] = __expf(sacc[nt][3] - nm1);
            sum0 += sacc[nt][0] + sacc[nt][1];
            sum1 += sacc[nt][2] + sacc[nt][3];
        }
        sum0 += __shfl_xor_sync(0xffffffffu, sum0, 1);
        sum0 += __shfl_xor_sync(0xffffffffu, sum0, 2);
        sum1 += __shfl_xor_sync(0xffffffffu, sum1, 1);
        sum1 += __shfl_xor_sync(0xffffffffu, sum1, 2);
        l0 = l0 * c0 + sum0; l1 = l1 * c1 + sum1;
#pragma unroll
        for (int nt = 0; nt < 8; nt++) {
            oacc[nt][0] *= c0; oacc[nt][1] *= c0;
            oacc[nt][2] *= c1; oacc[nt][3] *= c1;
        }

        // ---- P frags (fp16 hi/lo) ----
        uint32_t ph[4][4], pl[4][4];
#pragma unroll
        for (int kg = 0; kg < 4; kg++) {
            split2h(sacc[2 * kg][0],     sacc[2 * kg][1],     ph[kg][0], pl[kg][0]);
            split2h(sacc[2 * kg][2],     sacc[2 * kg][3],     ph[kg][1], pl[kg][1]);
            split2h(sacc[2 * kg + 1][0], sacc[2 * kg + 1][1], ph[kg][2], pl[kg][2]);
            split2h(sacc[2 * kg + 1][2], sacc[2 * kg + 1][3], ph[kg][3], pl[kg][3]);
        }

        // ---- O += P @ V (2-product) ----
#pragma unroll
        for (int kg = 0; kg < 4; kg++)
#pragma unroll
            for (int dg = 0; dg < 4; dg++) {
                uint32_t off = (uint32_t)((kg * 16 + ((lane >> 3) & 1) * 8 + r8) * AROWB +
                                          dg * 32 + ((lane >> 4) & 1) * 16);
                uint32_t vh0, vh1, vh2, vh3;
                LDSM_X4T(vh0, vh1, vh2, vh3, pVh + off);
                mma16816(oacc[dg * 2],     ph[kg], vh0, vh1);
                mma16816(oacc[dg * 2],     pl[kg], vh0, vh1);
                mma16816(oacc[dg * 2 + 1], ph[kg], vh2, vh3);
                mma16816(oacc[dg * 2 + 1], pl[kg], vh2, vh3);
            }

        __syncthreads();
        if (kt + 2 <= kthi) { load_kv(s, kt + 2); CP_COMMIT(); }
    }

    // ---- finalize ----
    float inv0 = 1.0f / l0, inv1 = 1.0f / l1;
    size_t row0 = (size_t)(b * SEQ + qt * 128 + w * 16 + g);
    size_t row1 = row0 + 8;
#pragma unroll
    for (int nt = 0; nt < 8; nt++) {
        int col = h * 64 + nt * 8 + 2 * qd;
        uint32_t hi, lo;
        split2h(oacc[nt][0] * inv0, oacc[nt][1] * inv0, hi, lo);
        *(uint32_t*)&g_Oh[row0 * WIDTH + col] = hi;
        *(uint32_t*)&g_Ol[row0 * WIDTH + col] = lo;
        split2h(oacc[nt][2] * inv1, oacc[nt][3] * inv1, hi, lo);
        *(uint32_t*)&g_Oh[row1 * WIDTH + col] = hi;
        *(uint32_t*)&g_Ol[row1 * WIDTH + col] = lo;
    }
}

// ---------------------------------------------------------------------------
// Launch
// ---------------------------------------------------------------------------
extern "C" void kernel_launch(void* const* d_in, const int* in_sizes, int n_in,
                              void* d_out, int out_size) {
    const float* x  = (const float*)d_in[0];
    const float* Wq = (const float*)d_in[1];
    const float* Wk = (const float*)d_in[2];
    const float* Wv = (const float*)d_in[3];
    const float* Wf = (const float*)d_in[4];
    const float* bf = (const float*)d_in[5];
    float* out = (float*)d_out;
    (void)in_sizes; (void)n_in; (void)out_size;

    __half *pAh, *pAl, *pWh, *pFh, *pQh, *pQl, *pOh, *pOl;
    cudaGetSymbolAddress((void**)&pAh, g_Ah);
    cudaGetSymbolAddress((void**)&pAl, g_Al);
    cudaGetSymbolAddress((void**)&pWh, g_Wh);
    cudaGetSymbolAddress((void**)&pFh, g_Fh);
    cudaGetSymbolAddress((void**)&pQh, g_Qh);
    cudaGetSymbolAddress((void**)&pQl, g_Ql);
    cudaGetSymbolAddress((void**)&pOh, g_Oh);
    cudaGetSymbolAddress((void**)&pOl, g_Ol);

    cudaFuncSetAttribute(mmagemm,
                         cudaFuncAttributeMaxDynamicSharedMemorySize, GEMM_SMEM);
    cudaFuncSetAttribute(attn_mma,
                         cudaFuncAttributeMaxDynamicSharedMemorySize, ATN_SMEM);

    convert_hl<<<TOK * WIDTH / 1024, 256>>>(x, pAh, pAl, TOK * WIDTH);
    convert_w<<<NQKV, 256>>>(Wq, Wk, Wv);
    convert_h<<<WIDTH * WIDTH / 1024, 256>>>(Wf, pFh, WIDTH * WIDTH);

    // QKV projection -> fp16 hi/lo qkv
    mmagemm<<<dim3(NQKV / 128, TOK / 128), 256, GEMM_SMEM>>>(
        pAh, pAl, pWh, nullptr, pQh, pQl, TOK, NQKV, WIDTH, nullptr);

    // tensor-core windowed attention -> fp16 hi/lo O
    attn_mma<<<dim3(SEQ / 128, NH, BATCH), 256, ATN_SMEM>>>();

    // output projection + bias -> fp32 out
    mmagemm<<<dim3(WIDTH / 128, TOK / 128), 256, GEMM_SMEM>>>(
        pOh, pOl, pFh, out, nullptr, nullptr, TOK, WIDTH, WIDTH, bf);
}

// round 9
// speedup vs baseline: 1.0701x; 1.0701x over previous
#include <cuda_runtime.h>
#include <cuda_fp16.h>
#include <cstdint>
#include <math.h>

// Problem constants
#define SEQ    2048
#define BATCH  2
#define WIDTH  1024
#define NH     16
#define HD     64
#define WIN    256
#define TOK    (BATCH*SEQ)     // 4096
#define NQKV   1152            // 1024 q + 64 k + 64 v

// ---------------------------------------------------------------------------
// Scratch (device globals).  fp16 split: activations hi+lo, weights hi only.
// ---------------------------------------------------------------------------
__device__ __half g_Ah[TOK * WIDTH],  g_Al[TOK * WIDTH];    // x hi/lo
__device__ __half g_Wh[NQKV * WIDTH];                        // [Wq;Wk;Wv] hi
__device__ __half g_Fh[WIDTH * WIDTH];                       // Wf hi
__device__ __half g_Qh[TOK * NQKV],  g_Ql[TOK * NQKV];       // qkv hi/lo
__device__ __half g_Oh[TOK * WIDTH], g_Ol[TOK * WIDTH];      // attn out hi/lo

// ---------------------------------------------------------------------------
// Helpers
// ---------------------------------------------------------------------------
__device__ __forceinline__ uint32_t smem_u32(const void* p) {
    uint32_t a;
    asm("{ .reg .u64 t; cvta.to.shared.u64 t, %1; cvt.u32.u64 %0, t; }"
        : "=r"(a) : "l"(p));
    return a;
}

#define CP_ASYNC16(sa, ga) \
    asm volatile("cp.async.cg.shared.global [%0], [%1], 16;" :: "r"(sa), "l"(ga))
#define CP_COMMIT() asm volatile("cp.async.commit_group;" ::: "memory")
#define CP_WAIT1()  asm volatile("cp.async.wait_group 1;" ::: "memory")
#define CP_WAIT0()  asm volatile("cp.async.wait_group 0;" ::: "memory")

#define LDSM_X4(r0, r1, r2, r3, addr) \
    asm volatile("ldmatrix.sync.aligned.m8n8.x4.shared.b16 {%0,%1,%2,%3}, [%4];" \
        : "=r"(r0), "=r"(r1), "=r"(r2), "=r"(r3) : "r"(addr))
#define LDSM_X4T(r0, r1, r2, r3, addr) \
    asm volatile("ldmatrix.sync.aligned.m8n8.x4.trans.shared.b16 {%0,%1,%2,%3}, [%4];" \
        : "=r"(r0), "=r"(r1), "=r"(r2), "=r"(r3) : "r"(addr))

__device__ __forceinline__ void mma16816(float* c, const uint32_t* a,
                                         uint32_t b0, uint32_t b1) {
    asm volatile(
        "mma.sync.aligned.m16n8k16.row.col.f32.f16.f16.f32 "
        "{%0,%1,%2,%3}, {%4,%5,%6,%7}, {%8,%9}, {%0,%1,%2,%3};"
        : "+f"(c[0]), "+f"(c[1]), "+f"(c[2]), "+f"(c[3])
        : "r"(a[0]), "r"(a[1]), "r"(a[2]), "r"(a[3]), "r"(b0), "r"(b1));
}

__device__ __forceinline__ uint32_t packh(__half a, __half b) {
    __half2 t; t.x = a; t.y = b;
    return *(uint32_t*)&t;
}
__device__ __forceinline__ void split2h(float a, float b, uint32_t& hi, uint32_t& lo) {
    __half ah = __float2half_rn(a), bh = __float2half_rn(b);
    hi = packh(ah, bh);
    lo = packh(__float2half_rn(a - __half2float(ah)),
               __float2half_rn(b - __half2float(bh)));
}
__device__ __forceinline__ void split_h(float v, __half& h, __half& l) {
    h = __float2half_rn(v);
    l = __float2half_rn(v - __half2float(h));
}

// ---------------------------------------------------------------------------
// fp32 -> fp16 conversions
// ---------------------------------------------------------------------------
__global__ void convert_hl(const float* __restrict__ src,
                           __half* __restrict__ hi, __half* __restrict__ lo, int n) {
    int i = (blockIdx.x * blockDim.x + threadIdx.x) * 4;
    if (i >= n) return;
    float4 v = *(const float4*)(src + i);
    __half h0, h1, h2, h3, l0, l1, l2, l3;
    split_h(v.x, h0, l0); split_h(v.y, h1, l1);
    split_h(v.z, h2, l2); split_h(v.w, h3, l3);
    __half2* H = (__half2*)(hi + i);
    __half2* L = (__half2*)(lo + i);
    H[0] = __half2(h0, h1); H[1] = __half2(h2, h3);
    L[0] = __half2(l0, l1); L[1] = __half2(l2, l3);
}

__global__ void convert_h(const float* __restrict__ src,
                          __half* __restrict__ hi, int n) {
    int i = (blockIdx.x * blockDim.x + threadIdx.x) * 4;
    if (i >= n) return;
    float4 v = *(const float4*)(src + i);
    __half2* H = (__half2*)(hi + i);
    H[0] = __half2(__float2half_rn(v.x), __float2half_rn(v.y));
    H[1] = __half2(__float2half_rn(v.z), __float2half_rn(v.w));
}

__global__ void convert_w(const float* __restrict__ Wq, const float* __restrict__ Wk,
                          const float* __restrict__ Wv) {
    int row = blockIdx.x;
    const float* src;
    if (row < 1024)      src = Wq + (size_t)row * WIDTH;
    else if (row < 1088) src = Wk + (size_t)(row - 1024) * WIDTH;
    else                 src = Wv + (size_t)(row - 1088) * WIDTH;
    int c = threadIdx.x * 4;
    float4 v = *(const float4*)(src + c);
    __half2* H = (__half2*)(g_Wh + (size_t)row * WIDTH + c);
    H[0] = __half2(__float2half_rn(v.x), __float2half_rn(v.y));
    H[1] = __half2(__float2half_rn(v.z), __float2half_rn(v.w));
}

// ---------------------------------------------------------------------------
// mma.sync GEMM: C = A @ B^T (+bias).  A = Ah + Al (fp16 x2), B = Bh.
// 128x128x32 tile, 8 warps as 2(M)x4(N), 3-stage cp.async pipeline,
// SINGLE barrier per iteration, 2 CTAs/SM.
// ---------------------------------------------------------------------------
#define BK 32
#define ROWB 80
#define ARR_B (128 * ROWB)            // 10240 B
#define STAGE_B (3 * ARR_B)           // Ah | Al | Bh = 30720 B
#define GEMM_SMEM (3 * STAGE_B)       // 92160 B -> 2 CTAs/SM

__global__ __launch_bounds__(256, 2)
void mmagemm(const __half* __restrict__ Ah, const __half* __restrict__ Al,
             const __half* __restrict__ Bh,
             float* __restrict__ C,
             __half* __restrict__ Ch, __half* __restrict__ Cl,
             int M, int N, int K, const float* __restrict__ bias) {
    extern __shared__ char smem[];
    uint32_t sb = smem_u32(smem);
    const int tid  = threadIdx.x;
    const int lane = tid & 31;
    const int wid  = tid >> 5;
    const int wm   = wid >> 2;        // 0..1  (M, 64 rows each)
    const int wn   = wid & 3;         // 0..3  (N, 32 cols each)
    const int m0 = blockIdx.y * 128;
    const int n0 = blockIdx.x * 128;
    const int NK = K / BK;
    const size_t RS = (size_t)K * 2;

    const int crow = tid >> 1;
    const int ccol = (tid & 1) * 2;
    const uint32_t s_off0 = crow * ROWB + ccol * 16;
    const char* gA0 = (const char*)Ah + (size_t)(m0 + crow) * RS + ccol * 16;
    const char* gA1 = (const char*)Al + (size_t)(m0 + crow) * RS + ccol * 16;
    const char* gB0 = (const char*)Bh + (size_t)(n0 + crow) * RS + ccol * 16;

    auto load_stage = [&](int s, int it) {
        uint32_t st = sb + s * STAGE_B;
        size_t kb = (size_t)it * (BK * 2);
        CP_ASYNC16(st + 0 * ARR_B + s_off0,      gA0 + kb);
        CP_ASYNC16(st + 0 * ARR_B + s_off0 + 16, gA0 + kb + 16);
        CP_ASYNC16(st + 1 * ARR_B + s_off0,      gA1 + kb);
        CP_ASYNC16(st + 1 * ARR_B + s_off0 + 16, gA1 + kb + 16);
        CP_ASYNC16(st + 2 * ARR_B + s_off0,      gB0 + kb);
        CP_ASYNC16(st + 2 * ARR_B + s_off0 + 16, gB0 + kb + 16);
    };

    float acc[4][4][4];
#pragma unroll
    for (int i = 0; i < 4; i++)
#pragma unroll
        for (int j = 0; j < 4; j++)
#pragma unroll
            for (int q = 0; q < 4; q++) acc[i][j][q] = 0.f;

    const int asub = lane >> 3;
    const int a_row_in = (lane & 7) + 8 * (asub & 1);
    const int a_chunk  = asub >> 1;
    const int b_row_in = (lane & 7) + 8 * (asub >> 1);
    const int b_chunk  = asub & 1;

    load_stage(0, 0); CP_COMMIT();
    load_stage(1, 1); CP_COMMIT();

    for (int it = 0; it < NK; ++it) {
        if (it + 1 < NK) CP_WAIT1(); else CP_WAIT0();
        __syncthreads();
        // Stage (it+2)%3 == (it-1)%3: its readers all finished before the
        // barrier above, so overwriting it now is race-free.
        if (it + 2 < NK) { load_stage((it + 2) % 3, it + 2); CP_COMMIT(); }

        uint32_t st  = sb + (it % 3) * STAGE_B;
        uint32_t pAh = st;
        uint32_t pAl = st + ARR_B;
        uint32_t pBh = st + 2 * ARR_B;

#pragma unroll
        for (int kk = 0; kk < 2; kk++) {
            uint32_t ah[4][4], al[4][4], bh[2][4];
#pragma unroll
            for (int mt = 0; mt < 4; mt++) {
                uint32_t off = (uint32_t)((wm * 64 + mt * 16 + a_row_in) * ROWB +
                                          (kk * 2 + a_chunk) * 16);
                LDSM_X4(ah[mt][0], ah[mt][1], ah[mt][2], ah[mt][3], pAh + off);
                LDSM_X4(al[mt][0], al[mt][1], al[mt][2], al[mt][3], pAl + off);
            }
#pragma unroll
            for (int p = 0; p < 2; p++) {
                uint32_t off = (uint32_t)((wn * 32 + p * 16 + b_row_in) * ROWB +
                                          (kk * 2 + b_chunk) * 16);
                LDSM_X4(bh[p][0], bh[p][1], bh[p][2], bh[p][3], pBh + off);
            }
#pragma unroll
            for (int mt = 0; mt < 4; mt++)
#pragma unroll
                for (int p = 0; p < 2; p++)
#pragma unroll
                    for (int hh = 0; hh < 2; hh++) {
                        int nt = p * 2 + hh;
                        mma16816(acc[mt][nt], ah[mt], bh[p][hh * 2], bh[p][hh * 2 + 1]);
                        mma16816(acc[mt][nt], al[mt], bh[p][hh * 2], bh[p][hh * 2 + 1]);
                    }
        }
    }

    const int gid = lane >> 2;
    const int qid = lane & 3;
#pragma unroll
    for (int mt = 0; mt < 4; mt++) {
        int r0 = m0 + wm * 64 + mt * 16 + gid;
#pragma unroll
        for (int nt = 0; nt < 4; nt++) {
            int c = n0 + wn * 32 + nt * 8 + qid * 2;
            if (C) {
                float b0 = 0.f, b1 = 0.f;
                if (bias) { b0 = bias[c]; b1 = bias[c + 1]; }
                *(float2*)&C[(size_t)r0 * N + c] =
                    make_float2(acc[mt][nt][0] + b0, acc[mt][nt][1] + b1);
                *(float2*)&C[(size_t)(r0 + 8) * N + c] =
                    make_float2(acc[mt][nt][2] + b0, acc[mt][nt][3] + b1);
            } else {
                uint32_t hi, lo;
                split2h(acc[mt][nt][0], acc[mt][nt][1], hi, lo);
                *(uint32_t*)&Ch[(size_t)r0 * N + c] = hi;
                *(uint32_t*)&Cl[(size_t)r0 * N + c] = lo;
                split2h(acc[mt][nt][2], acc[mt][nt][3], hi, lo);
                *(uint32_t*)&Ch[(size_t)(r0 + 8) * N + c] = hi;
                *(uint32_t*)&Cl[(size_t)(r0 + 8) * N + c] = lo;
            }
        }
    }
}

// ---------------------------------------------------------------------------
// Tensor-core windowed MQA flash attention (R7 config: 64 q rows, 128 thr,
// 3 CTAs/SM).  S 3-product fp16; PV 2-product.  KV double-buffered.
// ---------------------------------------------------------------------------
#define AROWB 144
#define ATN_ARR   (64 * AROWB)
#define ATN_SQH   0
#define ATN_SQL   ATN_ARR
#define ATN_STG   (2 * ATN_ARR)
#define ATN_STGSZ (3 * ATN_ARR)       // Kh | Kl | Vh
#define ATN_SMEM  (ATN_STG + 2 * ATN_STGSZ)   // 73728 B -> 3 CTAs/SM

__global__ __launch_bounds__(128, 3)
void attn_mma() {
    extern __shared__ char smc[];
    uint32_t sb = smem_u32(smc);
    const int qt = blockIdx.x, h = blockIdx.y, b = blockIdx.z;
    const int tid = threadIdx.x, lane = tid & 31, w = tid >> 5;
    const int g = lane >> 2, qd = lane & 3;
    const int r8 = lane & 7;

    {
        const char* srcH = (const char*)g_Qh + (size_t)(b * SEQ + qt * 64) * 2304 + h * 128;
        const char* srcL = (const char*)g_Ql + (size_t)(b * SEQ + qt * 64) * 2304 + h * 128;
#pragma unroll
        for (int j = 0; j < 4; j++) {
            int lin = j * 128 + tid, row = lin >> 3, ch = lin & 7;
            CP_ASYNC16(sb + ATN_SQH + row * AROWB + ch * 16,
                       srcH + (size_t)row * 2304 + ch * 16);
            CP_ASYNC16(sb + ATN_SQL + row * AROWB + ch * 16,
                       srcL + (size_t)row * 2304 + ch * 16);
        }
    }

    auto load_kv = [&](int s, int kt) {
        size_t kb = (size_t)(b * SEQ + kt * 64) * 2304;
        uint32_t st = sb + ATN_STG + s * ATN_STGSZ;
#pragma unroll
        for (int j = 0; j < 12; j++) {
            int arr = j >> 2, lin = (j & 3) * 128 + tid;
            int row = lin >> 3, ch = lin & 7;
            const char* base = (arr == 0) ? (const char*)g_Qh + 2048
                             : (arr == 1) ? (const char*)g_Ql + 2048
                                          : (const char*)g_Qh + 2176;
            CP_ASYNC16(st + arr * ATN_ARR + row * AROWB + ch * 16,
                       base + kb + (size_t)row * 2304 + ch * 16);
        }
    };

    int ktlo = qt - 4; if (ktlo < 0) ktlo = 0;
    int kthi = qt + 4; if (kthi > SEQ / 64 - 1) kthi = SEQ / 64 - 1;

    load_kv(0, ktlo); CP_COMMIT();
    if (ktlo < kthi) { load_kv(1, ktlo + 1); CP_COMMIT(); }

    uint32_t qh[4][4], ql[4][4];
    float oacc[8][4];
#pragma unroll
    for (int i = 0; i < 8; i++)
#pragma unroll
        for (int j = 0; j < 4; j++) oacc[i][j] = 0.f;
    float m0 = -1e30f, m1 = -1e30f, l0 = 0.f, l1 = 0.f;

    for (int kt = ktlo; kt <= kthi; kt++) {
        int s = (kt - ktlo) & 1;
        if (kt < kthi) CP_WAIT1(); else CP_WAIT0();
        __syncthreads();

        if (kt == ktlo) {
#pragma unroll
            for (int ks = 0; ks < 4; ks++) {
                uint32_t off = (uint32_t)((w * 16 + (lane & 15)) * AROWB +
                                          ks * 32 + (lane >> 4) * 16);
                LDSM_X4(qh[ks][0], qh[ks][1], qh[ks][2], qh[ks][3], sb + ATN_SQH + off);
                LDSM_X4(ql[ks][0], ql[ks][1], ql[ks][2], ql[ks][3], sb + ATN_SQL + off);
            }
        }

        uint32_t stg = sb + ATN_STG + s * ATN_STGSZ;
        uint32_t pKh = stg, pKl = stg + ATN_ARR;
        uint32_t pVh = stg + 2 * ATN_ARR;

        float sacc[8][4];
#pragma unroll
        for (int i = 0; i < 8; i++)
#pragma unroll
            for (int j = 0; j < 4; j++) sacc[i][j] = 0.f;

#pragma unroll
        for (int ks = 0; ks < 4; ks++)
#pragma unroll
            for (int sg = 0; sg < 4; sg++) {
                uint32_t off = (uint32_t)((sg * 16 + ((lane >> 4) & 1) * 8 + r8) * AROWB +
                                          ks * 32 + ((lane >> 3) & 1) * 16);
                uint32_t kh0, kh1, kh2, kh3, kl0, kl1, kl2, kl3;
                LDSM_X4(kh0, kh1, kh2, kh3, pKh + off);
                LDSM_X4(kl0, kl1, kl2, kl3, pKl + off);
                mma16816(sacc[sg * 2],     qh[ks], kh0, kh1);
                mma16816(sacc[sg * 2],     qh[ks], kl0, kl1);
                mma16816(sacc[sg * 2],     ql[ks], kh0, kh1);
                mma16816(sacc[sg * 2 + 1], qh[ks], kh2, kh3);
                mma16816(sacc[sg * 2 + 1], qh[ks], kl2, kl3);
                mma16816(sacc[sg * 2 + 1], ql[ks], kh2, kh3);
            }

        int rel = kt - qt;
#pragma unroll
        for (int nt = 0; nt < 8; nt++)
#pragma unroll
            for (int e = 0; e < 4; e++) sacc[nt][e] *= 0.125f;
        if (rel == 4 || rel == -4) {
#pragma unroll
            for (int nt = 0; nt < 8; nt++)
#pragma unroll
                for (int e = 0; e < 4; e++) {
                    int ri = w * 16 + g + ((e >= 2) ? 8 : 0);
                    int cj = nt * 8 + 2 * qd + (e & 1);
                    bool ok = (rel == 4) ? (cj <= ri) : (cj >= ri);
                    if (!ok) sacc[nt][e] = -1e30f;
                }
        }

        float rm0 = -1e30f, rm1 = -1e30f;
#pragma unroll
        for (int nt = 0; nt < 8; nt++) {
            rm0 = fmaxf(rm0, fmaxf(sacc[nt][0], sacc[nt][1]));
            rm1 = fmaxf(rm1, fmaxf(sacc[nt][2], sacc[nt][3]));
        }
        rm0 = fmaxf(rm0, __shfl_xor_sync(0xffffffffu, rm0, 1));
        rm0 = fmaxf(rm0, __shfl_xor_sync(0xffffffffu, rm0, 2));
        rm1 = fmaxf(rm1, __shfl_xor_sync(0xffffffffu, rm1, 1));
        rm1 = fmaxf(rm1, __shfl_xor_sync(0xffffffffu, rm1, 2));
        float nm0 = fmaxf(m0, rm0), nm1 = fmaxf(m1, rm1);
        float c0 = __expf(m0 - nm0), c1 = __expf(m1 - nm1);
        m0 = nm0; m1 = nm1;

        float sum0 = 0.f, sum1 = 0.f;
#pragma unroll
        for (int nt = 0; nt < 8; nt++) {
            sacc[nt][0] = __expf(sacc[nt][0] - nm0);
            sacc[nt][1] = __expf(sacc[nt][1] - nm0);
            sacc[nt][2] = __expf(sacc[nt][2] - nm1);
            sacc[nt][3] = __expf(sacc[nt][3] - nm1);
            sum0 += sacc[nt][0] + sacc[nt][1];
            sum1 += sacc[nt][2] + sacc[nt][3];
        }
        sum0 += __shfl_xor_sync(0xffffffffu, sum0, 1);
        sum0 += __shfl_xor_sync(0xffffffffu, sum0, 2);
        sum1 += __shfl_xor_sync(0xffffffffu, sum1, 1);
        sum1 += __shfl_xor_sync(0xffffffffu, sum1, 2);
        l0 = l0 * c0 + sum0; l1 = l1 * c1 + sum1;
#pragma unroll
        for (int nt = 0; nt < 8; nt++) {
            oacc[nt][0] *= c0; oacc[nt][1] *= c0;
            oacc[nt][2] *= c1; oacc[nt][3] *= c1;
        }

        uint32_t ph[4][4], pl[4][4];
#pragma unroll
        for (int kg = 0; kg < 4; kg++) {
            split2h(sacc[2 * kg][0],     sacc[2 * kg][1],     ph[kg][0], pl[kg][0]);
            split2h(sacc[2 * kg][2],     sacc[2 * kg][3],     ph[kg][1], pl[kg][1]);
            split2h(sacc[2 * kg + 1][0], sacc[2 * kg + 1][1], ph[kg][2], pl[kg][2]);
            split2h(sacc[2 * kg + 1][2], sacc[2 * kg + 1][3], ph[kg][3], pl[kg][3]);
        }

#pragma unroll
        for (int kg = 0; kg < 4; kg++)
#pragma unroll
            for (int dg = 0; dg < 4; dg++) {
                uint32_t off = (uint32_t)((kg * 16 + ((lane >> 3) & 1) * 8 + r8) * AROWB +
                                          dg * 32 + ((lane >> 4) & 1) * 16);
                uint32_t vh0, vh1, vh2, vh3;
                LDSM_X4T(vh0, vh1, vh2, vh3, pVh + off);
                mma16816(oacc[dg * 2],     ph[kg], vh0, vh1);
                mma16816(oacc[dg * 2],     pl[kg], vh0, vh1);
                mma16816(oacc[dg * 2 + 1], ph[kg], vh2, vh3);
                mma16816(oacc[dg * 2 + 1], pl[kg], vh2, vh3);
            }

        __syncthreads();
        if (kt + 2 <= kthi) { load_kv(s, kt + 2); CP_COMMIT(); }
    }

    float inv0 = 1.0f / l0, inv1 = 1.0f / l1;
    size_t row0 = (size_t)(b * SEQ + qt * 64 + w * 16 + g);
    size_t row1 = row0 + 8;
#pragma unroll
    for (int nt = 0; nt < 8; nt++) {
        int col = h * 64 + nt * 8 + 2 * qd;
        uint32_t hi, lo;
        split2h(oacc[nt][0] * inv0, oacc[nt][1] * inv0, hi, lo);
        *(uint32_t*)&g_Oh[row0 * WIDTH + col] = hi;
        *(uint32_t*)&g_Ol[row0 * WIDTH + col] = lo;
        split2h(oacc[nt][2] * inv1, oacc[nt][3] * inv1, hi, lo);
        *(uint32_t*)&g_Oh[row1 * WIDTH + col] = hi;
        *(uint32_t*)&g_Ol[row1 * WIDTH + col] = lo;
    }
}

// ---------------------------------------------------------------------------
// Launch
// ---------------------------------------------------------------------------
extern "C" void kernel_launch(void* const* d_in, const int* in_sizes, int n_in,
                              void* d_out, int out_size) {
    const float* x  = (const float*)d_in[0];
    const float* Wq = (const float*)d_in[1];
    const float* Wk = (const float*)d_in[2];
    const float* Wv = (const float*)d_in[3];
    const float* Wf = (const float*)d_in[4];
    const float* bf = (const float*)d_in[5];
    float* out = (float*)d_out;
    (void)in_sizes; (void)n_in; (void)out_size;

    __half *pAh, *pAl, *pWh, *pFh, *pQh, *pQl, *pOh, *pOl;
    cudaGetSymbolAddress((void**)&pAh, g_Ah);
    cudaGetSymbolAddress((void**)&pAl, g_Al);
    cudaGetSymbolAddress((void**)&pWh, g_Wh);
    cudaGetSymbolAddress((void**)&pFh, g_Fh);
    cudaGetSymbolAddress((void**)&pQh, g_Qh);
    cudaGetSymbolAddress((void**)&pQl, g_Ql);
    cudaGetSymbolAddress((void**)&pOh, g_Oh);
    cudaGetSymbolAddress((void**)&pOl, g_Ol);

    cudaFuncSetAttribute(mmagemm,
                         cudaFuncAttributeMaxDynamicSharedMemorySize, GEMM_SMEM);
    cudaFuncSetAttribute(attn_mma,
                         cudaFuncAttributeMaxDynamicSharedMemorySize, ATN_SMEM);

    convert_hl<<<TOK * WIDTH / 1024, 256>>>(x, pAh, pAl, TOK * WIDTH);
    convert_w<<<NQKV, 256>>>(Wq, Wk, Wv);
    convert_h<<<WIDTH * WIDTH / 1024, 256>>>(Wf, pFh, WIDTH * WIDTH);

    // QKV projection -> fp16 hi/lo qkv
    mmagemm<<<dim3(NQKV / 128, TOK / 128), 256, GEMM_SMEM>>>(
        pAh, pAl, pWh, nullptr, pQh, pQl, TOK, NQKV, WIDTH, nullptr);

    // tensor-core windowed attention -> fp16 hi/lo O
    attn_mma<<<dim3(SEQ / 64, NH, BATCH), 128, ATN_SMEM>>>();

    // output projection + bias -> fp32 out
    mmagemm<<<dim3(WIDTH / 128, TOK / 128), 256, GEMM_SMEM>>>(
        pOh, pOl, pFh, out, nullptr, nullptr, TOK, WIDTH, WIDTH, bf);
}

// round 10
// speedup vs baseline: 1.0772x; 1.0066x over previous
#include <cuda_runtime.h>
#include <cuda_fp16.h>
#include <cstdint>
#include <math.h>

// Problem constants
#define SEQ    2048
#define BATCH  2
#define WIDTH  1024
#define NH     16
#define HD     64
#define WIN    256
#define TOK    (BATCH*SEQ)     // 4096
#define NQKV   1152            // 1024 q + 64 k + 64 v

// ---------------------------------------------------------------------------
// Scratch (device globals).  fp16 split: activations hi+lo, weights hi only.
// ---------------------------------------------------------------------------
__device__ __half g_Ah[TOK * WIDTH],  g_Al[TOK * WIDTH];    // x hi/lo
__device__ __half g_Wh[NQKV * WIDTH];                        // [Wq;Wk;Wv] hi
__device__ __half g_Fh[WIDTH * WIDTH];                       // Wf hi
__device__ __half g_Qh[TOK * NQKV],  g_Ql[TOK * NQKV];       // qkv hi/lo
__device__ __half g_Oh[TOK * WIDTH], g_Ol[TOK * WIDTH];      // attn out hi/lo

// ---------------------------------------------------------------------------
// Helpers
// ---------------------------------------------------------------------------
__device__ __forceinline__ uint32_t smem_u32(const void* p) {
    uint32_t a;
    asm("{ .reg .u64 t; cvta.to.shared.u64 t, %1; cvt.u32.u64 %0, t; }"
        : "=r"(a) : "l"(p));
    return a;
}

#define CP_ASYNC16(sa, ga) \
    asm volatile("cp.async.cg.shared.global [%0], [%1], 16;" :: "r"(sa), "l"(ga))
#define CP_COMMIT() asm volatile("cp.async.commit_group;" ::: "memory")
#define CP_WAIT1()  asm volatile("cp.async.wait_group 1;" ::: "memory")
#define CP_WAIT0()  asm volatile("cp.async.wait_group 0;" ::: "memory")

#define LDSM_X4(r0, r1, r2, r3, addr) \
    asm volatile("ldmatrix.sync.aligned.m8n8.x4.shared.b16 {%0,%1,%2,%3}, [%4];" \
        : "=r"(r0), "=r"(r1), "=r"(r2), "=r"(r3) : "r"(addr))
#define LDSM_X4T(r0, r1, r2, r3, addr) \
    asm volatile("ldmatrix.sync.aligned.m8n8.x4.trans.shared.b16 {%0,%1,%2,%3}, [%4];" \
        : "=r"(r0), "=r"(r1), "=r"(r2), "=r"(r3) : "r"(addr))

__device__ __forceinline__ void mma16816(float* c, const uint32_t* a,
                                         uint32_t b0, uint32_t b1) {
    asm volatile(
        "mma.sync.aligned.m16n8k16.row.col.f32.f16.f16.f32 "
        "{%0,%1,%2,%3}, {%4,%5,%6,%7}, {%8,%9}, {%0,%1,%2,%3};"
        : "+f"(c[0]), "+f"(c[1]), "+f"(c[2]), "+f"(c[3])
        : "r"(a[0]), "r"(a[1]), "r"(a[2]), "r"(a[3]), "r"(b0), "r"(b1));
}

__device__ __forceinline__ uint32_t packh(__half a, __half b) {
    __half2 t; t.x = a; t.y = b;
    return *(uint32_t*)&t;
}
__device__ __forceinline__ void split2h(float a, float b, uint32_t& hi, uint32_t& lo) {
    __half ah = __float2half_rn(a), bh = __float2half_rn(b);
    hi = packh(ah, bh);
    lo = packh(__float2half_rn(a - __half2float(ah)),
               __float2half_rn(b - __half2float(bh)));
}
__device__ __forceinline__ void split_h(float v, __half& h, __half& l) {
    h = __float2half_rn(v);
    l = __float2half_rn(v - __half2float(h));
}

// ---------------------------------------------------------------------------
// fp32 -> fp16 conversions
// ---------------------------------------------------------------------------
__global__ void convert_hl(const float* __restrict__ src,
                           __half* __restrict__ hi, __half* __restrict__ lo, int n) {
    int i = (blockIdx.x * blockDim.x + threadIdx.x) * 4;
    if (i >= n) return;
    float4 v = *(const float4*)(src + i);
    __half h0, h1, h2, h3, l0, l1, l2, l3;
    split_h(v.x, h0, l0); split_h(v.y, h1, l1);
    split_h(v.z, h2, l2); split_h(v.w, h3, l3);
    __half2* H = (__half2*)(hi + i);
    __half2* L = (__half2*)(lo + i);
    H[0] = __half2(h0, h1); H[1] = __half2(h2, h3);
    L[0] = __half2(l0, l1); L[1] = __half2(l2, l3);
}

__global__ void convert_h(const float* __restrict__ src,
                          __half* __restrict__ hi, int n) {
    int i = (blockIdx.x * blockDim.x + threadIdx.x) * 4;
    if (i >= n) return;
    float4 v = *(const float4*)(src + i);
    __half2* H = (__half2*)(hi + i);
    H[0] = __half2(__float2half_rn(v.x), __float2half_rn(v.y));
    H[1] = __half2(__float2half_rn(v.z), __float2half_rn(v.w));
}

__global__ void convert_w(const float* __restrict__ Wq, const float* __restrict__ Wk,
                          const float* __restrict__ Wv) {
    int row = blockIdx.x;
    const float* src;
    if (row < 1024)      src = Wq + (size_t)row * WIDTH;
    else if (row < 1088) src = Wk + (size_t)(row - 1024) * WIDTH;
    else                 src = Wv + (size_t)(row - 1088) * WIDTH;
    int c = threadIdx.x * 4;
    float4 v = *(const float4*)(src + c);
    __half2* H = (__half2*)(g_Wh + (size_t)row * WIDTH + c);
    H[0] = __half2(__float2half_rn(v.x), __float2half_rn(v.y));
    H[1] = __half2(__float2half_rn(v.z), __float2half_rn(v.w));
}

// ---------------------------------------------------------------------------
// mma.sync GEMM: C = A @ B^T (+bias).  A = Ah + Al (fp16 x2), B = Bh.
// 128x128x32 tile, 8 warps as 4(M)x2(N) (warp tile 32x64), 3-stage cp.async,
// single barrier per iteration, 2 CTAs/SM.
// ---------------------------------------------------------------------------
#define BK 32
#define ROWB 80
#define ARR_B (128 * ROWB)            // 10240 B
#define STAGE_B (3 * ARR_B)           // Ah | Al | Bh = 30720 B
#define GEMM_SMEM (3 * STAGE_B)       // 92160 B -> 2 CTAs/SM

__global__ __launch_bounds__(256, 2)
void mmagemm(const __half* __restrict__ Ah, const __half* __restrict__ Al,
             const __half* __restrict__ Bh,
             float* __restrict__ C,
             __half* __restrict__ Ch, __half* __restrict__ Cl,
             int M, int N, int K, const float* __restrict__ bias) {
    extern __shared__ char smem[];
    uint32_t sb = smem_u32(smem);
    const int tid  = threadIdx.x;
    const int lane = tid & 31;
    const int wid  = tid >> 5;
    const int wm   = wid & 3;         // 0..3  (M, 32 rows each)
    const int wn   = wid >> 2;        // 0..1  (N, 64 cols each)
    const int m0 = blockIdx.y * 128;
    const int n0 = blockIdx.x * 128;
    const int NK = K / BK;
    const size_t RS = (size_t)K * 2;

    const int crow = tid >> 1;
    const int ccol = (tid & 1) * 2;
    const uint32_t s_off0 = crow * ROWB + ccol * 16;
    const char* gA0 = (const char*)Ah + (size_t)(m0 + crow) * RS + ccol * 16;
    const char* gA1 = (const char*)Al + (size_t)(m0 + crow) * RS + ccol * 16;
    const char* gB0 = (const char*)Bh + (size_t)(n0 + crow) * RS + ccol * 16;

    auto load_stage = [&](int s, int it) {
        uint32_t st = sb + s * STAGE_B;
        size_t kb = (size_t)it * (BK * 2);
        CP_ASYNC16(st + 0 * ARR_B + s_off0,      gA0 + kb);
        CP_ASYNC16(st + 0 * ARR_B + s_off0 + 16, gA0 + kb + 16);
        CP_ASYNC16(st + 1 * ARR_B + s_off0,      gA1 + kb);
        CP_ASYNC16(st + 1 * ARR_B + s_off0 + 16, gA1 + kb + 16);
        CP_ASYNC16(st + 2 * ARR_B + s_off0,      gB0 + kb);
        CP_ASYNC16(st + 2 * ARR_B + s_off0 + 16, gB0 + kb + 16);
    };

    float acc[2][8][4];
#pragma unroll
    for (int i = 0; i < 2; i++)
#pragma unroll
        for (int j = 0; j < 8; j++)
#pragma unroll
            for (int q = 0; q < 4; q++) acc[i][j][q] = 0.f;

    const int asub = lane >> 3;
    const int a_row_in = (lane & 7) + 8 * (asub & 1);
    const int a_chunk  = asub >> 1;
    const int b_row_in = (lane & 7) + 8 * (asub >> 1);
    const int b_chunk  = asub & 1;

    load_stage(0, 0); CP_COMMIT();
    load_stage(1, 1); CP_COMMIT();

    for (int it = 0; it < NK; ++it) {
        if (it + 1 < NK) CP_WAIT1(); else CP_WAIT0();
        __syncthreads();
        // Stage (it+2)%3 == (it-1)%3: its readers finished before the barrier.
        if (it + 2 < NK) { load_stage((it + 2) % 3, it + 2); CP_COMMIT(); }

        uint32_t st  = sb + (it % 3) * STAGE_B;
        uint32_t pAh = st;
        uint32_t pAl = st + ARR_B;
        uint32_t pBh = st + 2 * ARR_B;

#pragma unroll
        for (int kk = 0; kk < 2; kk++) {
            uint32_t ah[2][4], al[2][4], bh[4][4];
#pragma unroll
            for (int mt = 0; mt < 2; mt++) {
                uint32_t off = (uint32_t)((wm * 32 + mt * 16 + a_row_in) * ROWB +
                                          (kk * 2 + a_chunk) * 16);
                LDSM_X4(ah[mt][0], ah[mt][1], ah[mt][2], ah[mt][3], pAh + off);
                LDSM_X4(al[mt][0], al[mt][1], al[mt][2], al[mt][3], pAl + off);
            }
#pragma unroll
            for (int p = 0; p < 4; p++) {
                uint32_t off = (uint32_t)((wn * 64 + p * 16 + b_row_in) * ROWB +
                                          (kk * 2 + b_chunk) * 16);
                LDSM_X4(bh[p][0], bh[p][1], bh[p][2], bh[p][3], pBh + off);
            }
#pragma unroll
            for (int mt = 0; mt < 2; mt++)
#pragma unroll
                for (int p = 0; p < 4; p++)
#pragma unroll
                    for (int hh = 0; hh < 2; hh++) {
                        int nt = p * 2 + hh;
                        mma16816(acc[mt][nt], ah[mt], bh[p][hh * 2], bh[p][hh * 2 + 1]);
                        mma16816(acc[mt][nt], al[mt], bh[p][hh * 2], bh[p][hh * 2 + 1]);
                    }
        }
    }

    const int gid = lane >> 2;
    const int qid = lane & 3;
#pragma unroll
    for (int mt = 0; mt < 2; mt++) {
        int r0 = m0 + wm * 32 + mt * 16 + gid;
#pragma unroll
        for (int nt = 0; nt < 8; nt++) {
            int c = n0 + wn * 64 + nt * 8 + qid * 2;
            if (C) {
                float b0 = 0.f, b1 = 0.f;
                if (bias) { b0 = bias[c]; b1 = bias[c + 1]; }
                *(float2*)&C[(size_t)r0 * N + c] =
                    make_float2(acc[mt][nt][0] + b0, acc[mt][nt][1] + b1);
                *(float2*)&C[(size_t)(r0 + 8) * N + c] =
                    make_float2(acc[mt][nt][2] + b0, acc[mt][nt][3] + b1);
            } else {
                uint32_t hi, lo;
                split2h(acc[mt][nt][0], acc[mt][nt][1], hi, lo);
                *(uint32_t*)&Ch[(size_t)r0 * N + c] = hi;
                *(uint32_t*)&Cl[(size_t)r0 * N + c] = lo;
                split2h(acc[mt][nt][2], acc[mt][nt][3], hi, lo);
                *(uint32_t*)&Ch[(size_t)(r0 + 8) * N + c] = hi;
                *(uint32_t*)&Cl[(size_t)(r0 + 8) * N + c] = lo;
            }
        }
    }
}

// ---------------------------------------------------------------------------
// Tensor-core windowed MQA flash attention (64 q rows, 128 thr, 3 CTAs/SM).
// S 3-product fp16; PV 2-product.  KV double-buffered.
// ---------------------------------------------------------------------------
#define AROWB 144
#define ATN_ARR   (64 * AROWB)
#define ATN_SQH   0
#define ATN_SQL   ATN_ARR
#define ATN_STG   (2 * ATN_ARR)
#define ATN_STGSZ (3 * ATN_ARR)       // Kh | Kl | Vh
#define ATN_SMEM  (ATN_STG + 2 * ATN_STGSZ)   // 73728 B -> 3 CTAs/SM

__global__ __launch_bounds__(128, 3)
void attn_mma() {
    extern __shared__ char smc[];
    uint32_t sb = smem_u32(smc);
    const int qt = blockIdx.x, h = blockIdx.y, b = blockIdx.z;
    const int tid = threadIdx.x, lane = tid & 31, w = tid >> 5;
    const int g = lane >> 2, qd = lane & 3;
    const int r8 = lane & 7;

    {
        const char* srcH = (const char*)g_Qh + (size_t)(b * SEQ + qt * 64) * 2304 + h * 128;
        const char* srcL = (const char*)g_Ql + (size_t)(b * SEQ + qt * 64) * 2304 + h * 128;
#pragma unroll
        for (int j = 0; j < 4; j++) {
            int lin = j * 128 + tid, row = lin >> 3, ch = lin & 7;
            CP_ASYNC16(sb + ATN_SQH + row * AROWB + ch * 16,
                       srcH + (size_t)row * 2304 + ch * 16);
            CP_ASYNC16(sb + ATN_SQL + row * AROWB + ch * 16,
                       srcL + (size_t)row * 2304 + ch * 16);
        }
    }

    auto load_kv = [&](int s, int kt) {
        size_t kb = (size_t)(b * SEQ + kt * 64) * 2304;
        uint32_t st = sb + ATN_STG + s * ATN_STGSZ;
#pragma unroll
        for (int j = 0; j < 12; j++) {
            int arr = j >> 2, lin = (j & 3) * 128 + tid;
            int row = lin >> 3, ch = lin & 7;
            const char* base = (arr == 0) ? (const char*)g_Qh + 2048
                             : (arr == 1) ? (const char*)g_Ql + 2048
                                          : (const char*)g_Qh + 2176;
            CP_ASYNC16(st + arr * ATN_ARR + row * AROWB + ch * 16,
                       base + kb + (size_t)row * 2304 + ch * 16);
        }
    };

    int ktlo = qt - 4; if (ktlo < 0) ktlo = 0;
    int kthi = qt + 4; if (kthi > SEQ / 64 - 1) kthi = SEQ / 64 - 1;

    load_kv(0, ktlo); CP_COMMIT();
    if (ktlo < kthi) { load_kv(1, ktlo + 1); CP_COMMIT(); }

    uint32_t qh[4][4], ql[4][4];
    float oacc[8][4];
#pragma unroll
    for (int i = 0; i < 8; i++)
#pragma unroll
        for (int j = 0; j < 4; j++) oacc[i][j] = 0.f;
    float m0 = -1e30f, m1 = -1e30f, l0 = 0.f, l1 = 0.f;

    for (int kt = ktlo; kt <= kthi; kt++) {
        int s = (kt - ktlo) & 1;
        if (kt < kthi) CP_WAIT1(); else CP_WAIT0();
        __syncthreads();

        if (kt == ktlo) {
#pragma unroll
            for (int ks = 0; ks < 4; ks++) {
                uint32_t off = (uint32_t)((w * 16 + (lane & 15)) * AROWB +
                                          ks * 32 + (lane >> 4) * 16);
                LDSM_X4(qh[ks][0], qh[ks][1], qh[ks][2], qh[ks][3], sb + ATN_SQH + off);
                LDSM_X4(ql[ks][0], ql[ks][1], ql[ks][2], ql[ks][3], sb + ATN_SQL + off);
            }
        }

        uint32_t stg = sb + ATN_STG + s * ATN_STGSZ;
        uint32_t pKh = stg, pKl = stg + ATN_ARR;
        uint32_t pVh = stg + 2 * ATN_ARR;

        float sacc[8][4];
#pragma unroll
        for (int i = 0; i < 8; i++)
#pragma unroll
            for (int j = 0; j < 4; j++) sacc[i][j] = 0.f;

#pragma unroll
        for (int ks = 0; ks < 4; ks++)
#pragma unroll
            for (int sg = 0; sg < 4; sg++) {
                uint32_t off = (uint32_t)((sg * 16 + ((lane >> 4) & 1) * 8 + r8) * AROWB +
                                          ks * 32 + ((lane >> 3) & 1) * 16);
                uint32_t kh0, kh1, kh2, kh3, kl0, kl1, kl2, kl3;
                LDSM_X4(kh0, kh1, kh2, kh3, pKh + off);
                LDSM_X4(kl0, kl1, kl2, kl3, pKl + off);
                mma16816(sacc[sg * 2],     qh[ks], kh0, kh1);
                mma16816(sacc[sg * 2],     qh[ks], kl0, kl1);
                mma16816(sacc[sg * 2],     ql[ks], kh0, kh1);
                mma16816(sacc[sg * 2 + 1], qh[ks], kh2, kh3);
                mma16816(sacc[sg * 2 + 1], qh[ks], kl2, kl3);
                mma16816(sacc[sg * 2 + 1], ql[ks], kh2, kh3);
            }

        int rel = kt - qt;
#pragma unroll
        for (int nt = 0; nt < 8; nt++)
#pragma unroll
            for (int e = 0; e < 4; e++) sacc[nt][e] *= 0.125f;
        if (rel == 4 || rel == -4) {
#pragma unroll
            for (int nt = 0; nt < 8; nt++)
#pragma unroll
                for (int e = 0; e < 4; e++) {
                    int ri = w * 16 + g + ((e >= 2) ? 8 : 0);
                    int cj = nt * 8 + 2 * qd + (e & 1);
                    bool ok = (rel == 4) ? (cj <= ri) : (cj >= ri);
                    if (!ok) sacc[nt][e] = -1e30f;
                }
        }

        float rm0 = -1e30f, rm1 = -1e30f;
#pragma unroll
        for (int nt = 0; nt < 8; nt++) {
            rm0 = fmaxf(rm0, fmaxf(sacc[nt][0], sacc[nt][1]));
            rm1 = fmaxf(rm1, fmaxf(sacc[nt][2], sacc[nt][3]));
        }
        rm0 = fmaxf(rm0, __shfl_xor_sync(0xffffffffu, rm0, 1));
        rm0 = fmaxf(rm0, __shfl_xor_sync(0xffffffffu, rm0, 2));
        rm1 = fmaxf(rm1, __shfl_xor_sync(0xffffffffu, rm1, 1));
        rm1 = fmaxf(rm1, __shfl_xor_sync(0xffffffffu, rm1, 2));
        float nm0 = fmaxf(m0, rm0), nm1 = fmaxf(m1, rm1);
        float c0 = __expf(m0 - nm0), c1 = __expf(m1 - nm1);
        m0 = nm0; m1 = nm1;

        float sum0 = 0.f, sum1 = 0.f;
#pragma unroll
        for (int nt = 0; nt < 8; nt++) {
            sacc[nt][0] = __expf(sacc[nt][0] - nm0);
            sacc[nt][1] = __expf(sacc[nt][1] - nm0);
            sacc[nt][2] = __expf(sacc[nt][2] - nm1);
            sacc[nt][3] = __expf(sacc[nt][3] - nm1);
            sum0 += sacc[nt][0] + sacc[nt][1];
            sum1 += sacc[nt][2] + sacc[nt][3];
        }
        sum0 += __shfl_xor_sync(0xffffffffu, sum0, 1);
        sum0 += __shfl_xor_sync(0xffffffffu, sum0, 2);
        sum1 += __shfl_xor_sync(0xffffffffu, sum1, 1);
        sum1 += __shfl_xor_sync(0xffffffffu, sum1, 2);
        l0 = l0 * c0 + sum0; l1 = l1 * c1 + sum1;
#pragma unroll
        for (int nt = 0; nt < 8; nt++) {
            oacc[nt][0] *= c0; oacc[nt][1] *= c0;
            oacc[nt][2] *= c1; oacc[nt][3] *= c1;
        }

        uint32_t ph[4][4], pl[4][4];
#pragma unroll
        for (int kg = 0; kg < 4; kg++) {
            split2h(sacc[2 * kg][0],     sacc[2 * kg][1],     ph[kg][0], pl[kg][0]);
            split2h(sacc[2 * kg][2],     sacc[2 * kg][3],     ph[kg][1], pl[kg][1]);
            split2h(sacc[2 * kg + 1][0], sacc[2 * kg + 1][1], ph[kg][2], pl[kg][2]);
            split2h(sacc[2 * kg + 1][2], sacc[2 * kg + 1][3], ph[kg][3], pl[kg][3]);
        }

#pragma unroll
        for (int kg = 0; kg < 4; kg++)
#pragma unroll
            for (int dg = 0; dg < 4; dg++) {
                uint32_t off = (uint32_t)((kg * 16 + ((lane >> 3) & 1) * 8 + r8) * AROWB +
                                          dg * 32 + ((lane >> 4) & 1) * 16);
                uint32_t vh0, vh1, vh2, vh3;
                LDSM_X4T(vh0, vh1, vh2, vh3, pVh + off);
                mma16816(oacc[dg * 2],     ph[kg], vh0, vh1);
                mma16816(oacc[dg * 2],     pl[kg], vh0, vh1);
                mma16816(oacc[dg * 2 + 1], ph[kg], vh2, vh3);
                mma16816(oacc[dg * 2 + 1], pl[kg], vh2, vh3);
            }

        __syncthreads();
        if (kt + 2 <= kthi) { load_kv(s, kt + 2); CP_COMMIT(); }
    }

    float inv0 = 1.0f / l0, inv1 = 1.0f / l1;
    size_t row0 = (size_t)(b * SEQ + qt * 64 + w * 16 + g);
    size_t row1 = row0 + 8;
#pragma unroll
    for (int nt = 0; nt < 8; nt++) {
        int col = h * 64 + nt * 8 + 2 * qd;
        uint32_t hi, lo;
        split2h(oacc[nt][0] * inv0, oacc[nt][1] * inv0, hi, lo);
        *(uint32_t*)&g_Oh[row0 * WIDTH + col] = hi;
        *(uint32_t*)&g_Ol[row0 * WIDTH + col] = lo;
        split2h(oacc[nt][2] * inv1, oacc[nt][3] * inv1, hi, lo);
        *(uint32_t*)&g_Oh[row1 * WIDTH + col] = hi;
        *(uint32_t*)&g_Ol[row1 * WIDTH + col] = lo;
    }
}

// ---------------------------------------------------------------------------
// Launch
// ---------------------------------------------------------------------------
extern "C" void kernel_launch(void* const* d_in, const int* in_sizes, int n_in,
                              void* d_out, int out_size) {
    const float* x  = (const float*)d_in[0];
    const float* Wq = (const float*)d_in[1];
    const float* Wk = (const float*)d_in[2];
    const float* Wv = (const float*)d_in[3];
    const float* Wf = (const float*)d_in[4];
    const float* bf = (const float*)d_in[5];
    float* out = (float*)d_out;
    (void)in_sizes; (void)n_in; (void)out_size;

    __half *pAh, *pAl, *pWh, *pFh, *pQh, *pQl, *pOh, *pOl;
    cudaGetSymbolAddress((void**)&pAh, g_Ah);
    cudaGetSymbolAddress((void**)&pAl, g_Al);
    cudaGetSymbolAddress((void**)&pWh, g_Wh);
    cudaGetSymbolAddress((void**)&pFh, g_Fh);
    cudaGetSymbolAddress((void**)&pQh, g_Qh);
    cudaGetSymbolAddress((void**)&pQl, g_Ql);
    cudaGetSymbolAddress((void**)&pOh, g_Oh);
    cudaGetSymbolAddress((void**)&pOl, g_Ol);

    cudaFuncSetAttribute(mmagemm,
                         cudaFuncAttributeMaxDynamicSharedMemorySize, GEMM_SMEM);
    cudaFuncSetAttribute(attn_mma,
                         cudaFuncAttributeMaxDynamicSharedMemorySize, ATN_SMEM);

    convert_hl<<<TOK * WIDTH / 1024, 256>>>(x, pAh, pAl, TOK * WIDTH);
    convert_w<<<NQKV, 256>>>(Wq, Wk, Wv);
    convert_h<<<WIDTH * WIDTH / 1024, 256>>>(Wf, pFh, WIDTH * WIDTH);

    // QKV projection -> fp16 hi/lo qkv
    mmagemm<<<dim3(NQKV / 128, TOK / 128), 256, GEMM_SMEM>>>(
        pAh, pAl, pWh, nullptr, pQh, pQl, TOK, NQKV, WIDTH, nullptr);

    // tensor-core windowed attention -> fp16 hi/lo O
    attn_mma<<<dim3(SEQ / 64, NH, BATCH), 128, ATN_SMEM>>>();

    // output projection + bias -> fp32 out
    mmagemm<<<dim3(WIDTH / 128, TOK / 128), 256, GEMM_SMEM>>>(
        pOh, pOl, pFh, out, nullptr, nullptr, TOK, WIDTH, WIDTH, bf);
}

// round 11
// speedup vs baseline: 1.1523x; 1.0697x over previous
#include <cuda_runtime.h>
#include <cuda_fp16.h>
#include <cstdint>
#include <math.h>

// Problem constants
#define SEQ    2048
#define BATCH  2
#define WIDTH  1024
#define NH     16
#define HD     64
#define WIN    256
#define TOK    (BATCH*SEQ)     // 4096
#define NQKV   1152            // 1024 q + 64 k + 64 v

// ---------------------------------------------------------------------------
// Scratch (device globals).  fp16 split: activations hi+lo, weights hi only.
// ---------------------------------------------------------------------------
__device__ __half g_Ah[TOK * WIDTH],  g_Al[TOK * WIDTH];    // x hi/lo
__device__ __half g_Wh[NQKV * WIDTH];                        // [Wq;Wk;Wv] hi
__device__ __half g_Fh[WIDTH * WIDTH];                       // Wf hi
__device__ __half g_Qh[TOK * NQKV],  g_Ql[TOK * NQKV];       // qkv hi/lo
__device__ __half g_Oh[TOK * WIDTH], g_Ol[TOK * WIDTH];      // attn out hi/lo

// ---------------------------------------------------------------------------
// Helpers
// ---------------------------------------------------------------------------
__device__ __forceinline__ uint32_t smem_u32(const void* p) {
    uint32_t a;
    asm("{ .reg .u64 t; cvta.to.shared.u64 t, %1; cvt.u32.u64 %0, t; }"
        : "=r"(a) : "l"(p));
    return a;
}

#define CP_ASYNC16(sa, ga) \
    asm volatile("cp.async.cg.shared.global [%0], [%1], 16;" :: "r"(sa), "l"(ga))
#define CP_COMMIT() asm volatile("cp.async.commit_group;" ::: "memory")
#define CP_WAIT1()  asm volatile("cp.async.wait_group 1;" ::: "memory")
#define CP_WAIT0()  asm volatile("cp.async.wait_group 0;" ::: "memory")

#define LDSM_X4(r0, r1, r2, r3, addr) \
    asm volatile("ldmatrix.sync.aligned.m8n8.x4.shared.b16 {%0,%1,%2,%3}, [%4];" \
        : "=r"(r0), "=r"(r1), "=r"(r2), "=r"(r3) : "r"(addr))
#define LDSM_X4T(r0, r1, r2, r3, addr) \
    asm volatile("ldmatrix.sync.aligned.m8n8.x4.trans.shared.b16 {%0,%1,%2,%3}, [%4];" \
        : "=r"(r0), "=r"(r1), "=r"(r2), "=r"(r3) : "r"(addr))

__device__ __forceinline__ void mma16816(float* c, const uint32_t* a,
                                         uint32_t b0, uint32_t b1) {
    asm volatile(
        "mma.sync.aligned.m16n8k16.row.col.f32.f16.f16.f32 "
        "{%0,%1,%2,%3}, {%4,%5,%6,%7}, {%8,%9}, {%0,%1,%2,%3};"
        : "+f"(c[0]), "+f"(c[1]), "+f"(c[2]), "+f"(c[3])
        : "r"(a[0]), "r"(a[1]), "r"(a[2]), "r"(a[3]), "r"(b0), "r"(b1));
}

__device__ __forceinline__ uint32_t packh(__half a, __half b) {
    __half2 t; t.x = a; t.y = b;
    return *(uint32_t*)&t;
}
__device__ __forceinline__ uint32_t pack2h(float a, float b) {
    return packh(__float2half_rn(a), __float2half_rn(b));
}
__device__ __forceinline__ void split2h(float a, float b, uint32_t& hi, uint32_t& lo) {
    __half ah = __float2half_rn(a), bh = __float2half_rn(b);
    hi = packh(ah, bh);
    lo = packh(__float2half_rn(a - __half2float(ah)),
               __float2half_rn(b - __half2float(bh)));
}
__device__ __forceinline__ void split_h(float v, __half& h, __half& l) {
    h = __float2half_rn(v);
    l = __float2half_rn(v - __half2float(h));
}

// ---------------------------------------------------------------------------
// One fused conversion kernel: x -> Ah/Al ; [Wq;Wk;Wv] -> Wh ; Wf -> Fh.
// ---------------------------------------------------------------------------
#define NXQ (TOK * WIDTH / 4)         // 1048576 quads
#define NWQ (NQKV * WIDTH / 4)        // 294912
#define NFQ (WIDTH * WIDTH / 4)       // 262144
#define NALLQ (NXQ + NWQ + NFQ)

__global__ void convert_all(const float* __restrict__ x,
                            const float* __restrict__ Wq,
                            const float* __restrict__ Wk,
                            const float* __restrict__ Wv,
                            const float* __restrict__ Wf) {
    int q = blockIdx.x * blockDim.x + threadIdx.x;
    if (q < NXQ) {
        int i = q * 4;
        float4 v = *(const float4*)(x + i);
        __half h0, h1, h2, h3, l0, l1, l2, l3;
        split_h(v.x, h0, l0); split_h(v.y, h1, l1);
        split_h(v.z, h2, l2); split_h(v.w, h3, l3);
        __half2* H = (__half2*)(g_Ah + i);
        __half2* L = (__half2*)(g_Al + i);
        H[0] = __half2(h0, h1); H[1] = __half2(h2, h3);
        L[0] = __half2(l0, l1); L[1] = __half2(l2, l3);
    } else if (q < NXQ + NWQ) {
        int e = (q - NXQ) * 4;
        int row = e >> 10, c = e & 1023;
        const float* src;
        if (row < 1024)      src = Wq + (size_t)row * WIDTH + c;
        else if (row < 1088) src = Wk + (size_t)(row - 1024) * WIDTH + c;
        else                 src = Wv + (size_t)(row - 1088) * WIDTH + c;
        float4 v = *(const float4*)src;
        __half2* H = (__half2*)(g_Wh + e);
        H[0] = __half2(__float2half_rn(v.x), __float2half_rn(v.y));
        H[1] = __half2(__float2half_rn(v.z), __float2half_rn(v.w));
    } else if (q < NALLQ) {
        int i = (q - NXQ - NWQ) * 4;
        float4 v = *(const float4*)(Wf + i);
        __half2* H = (__half2*)(g_Fh + i);
        H[0] = __half2(__float2half_rn(v.x), __float2half_rn(v.y));
        H[1] = __half2(__float2half_rn(v.z), __float2half_rn(v.w));
    }
}

// ---------------------------------------------------------------------------
// mma.sync GEMM: C = A @ B^T (+bias).  A = Ah + Al (fp16 x2), B = Bh.
// 128x128x32 tile, 8 warps as 4(M)x2(N), 3-stage cp.async, single barrier,
// 2 CTAs/SM.  (R10 measured-best config.)
// ---------------------------------------------------------------------------
#define BK 32
#define ROWB 80
#define ARR_B (128 * ROWB)            // 10240 B
#define STAGE_B (3 * ARR_B)           // Ah | Al | Bh = 30720 B
#define GEMM_SMEM (3 * STAGE_B)       // 92160 B -> 2 CTAs/SM

__global__ __launch_bounds__(256, 2)
void mmagemm(const __half* __restrict__ Ah, const __half* __restrict__ Al,
             const __half* __restrict__ Bh,
             float* __restrict__ C,
             __half* __restrict__ Ch, __half* __restrict__ Cl,
             int M, int N, int K, const float* __restrict__ bias) {
    extern __shared__ char smem[];
    uint32_t sb = smem_u32(smem);
    const int tid  = threadIdx.x;
    const int lane = tid & 31;
    const int wid  = tid >> 5;
    const int wm   = wid & 3;
    const int wn   = wid >> 2;
    const int m0 = blockIdx.y * 128;
    const int n0 = blockIdx.x * 128;
    const int NK = K / BK;
    const size_t RS = (size_t)K * 2;

    const int crow = tid >> 1;
    const int ccol = (tid & 1) * 2;
    const uint32_t s_off0 = crow * ROWB + ccol * 16;
    const char* gA0 = (const char*)Ah + (size_t)(m0 + crow) * RS + ccol * 16;
    const char* gA1 = (const char*)Al + (size_t)(m0 + crow) * RS + ccol * 16;
    const char* gB0 = (const char*)Bh + (size_t)(n0 + crow) * RS + ccol * 16;

    auto load_stage = [&](int s, int it) {
        uint32_t st = sb + s * STAGE_B;
        size_t kb = (size_t)it * (BK * 2);
        CP_ASYNC16(st + 0 * ARR_B + s_off0,      gA0 + kb);
        CP_ASYNC16(st + 0 * ARR_B + s_off0 + 16, gA0 + kb + 16);
        CP_ASYNC16(st + 1 * ARR_B + s_off0,      gA1 + kb);
        CP_ASYNC16(st + 1 * ARR_B + s_off0 + 16, gA1 + kb + 16);
        CP_ASYNC16(st + 2 * ARR_B + s_off0,      gB0 + kb);
        CP_ASYNC16(st + 2 * ARR_B + s_off0 + 16, gB0 + kb + 16);
    };

    float acc[2][8][4];
#pragma unroll
    for (int i = 0; i < 2; i++)
#pragma unroll
        for (int j = 0; j < 8; j++)
#pragma unroll
            for (int q = 0; q < 4; q++) acc[i][j][q] = 0.f;

    const int asub = lane >> 3;
    const int a_row_in = (lane & 7) + 8 * (asub & 1);
    const int a_chunk  = asub >> 1;
    const int b_row_in = (lane & 7) + 8 * (asub >> 1);
    const int b_chunk  = asub & 1;

    load_stage(0, 0); CP_COMMIT();
    load_stage(1, 1); CP_COMMIT();

    for (int it = 0; it < NK; ++it) {
        if (it + 1 < NK) CP_WAIT1(); else CP_WAIT0();
        __syncthreads();
        if (it + 2 < NK) { load_stage((it + 2) % 3, it + 2); CP_COMMIT(); }

        uint32_t st  = sb + (it % 3) * STAGE_B;
        uint32_t pAh = st;
        uint32_t pAl = st + ARR_B;
        uint32_t pBh = st + 2 * ARR_B;

#pragma unroll
        for (int kk = 0; kk < 2; kk++) {
            uint32_t ah[2][4], al[2][4], bh[4][4];
#pragma unroll
            for (int mt = 0; mt < 2; mt++) {
                uint32_t off = (uint32_t)((wm * 32 + mt * 16 + a_row_in) * ROWB +
                                          (kk * 2 + a_chunk) * 16);
                LDSM_X4(ah[mt][0], ah[mt][1], ah[mt][2], ah[mt][3], pAh + off);
                LDSM_X4(al[mt][0], al[mt][1], al[mt][2], al[mt][3], pAl + off);
            }
#pragma unroll
            for (int p = 0; p < 4; p++) {
                uint32_t off = (uint32_t)((wn * 64 + p * 16 + b_row_in) * ROWB +
                                          (kk * 2 + b_chunk) * 16);
                LDSM_X4(bh[p][0], bh[p][1], bh[p][2], bh[p][3], pBh + off);
            }
#pragma unroll
            for (int mt = 0; mt < 2; mt++)
#pragma unroll
                for (int p = 0; p < 4; p++)
#pragma unroll
                    for (int hh = 0; hh < 2; hh++) {
                        int nt = p * 2 + hh;
                        mma16816(acc[mt][nt], ah[mt], bh[p][hh * 2], bh[p][hh * 2 + 1]);
                        mma16816(acc[mt][nt], al[mt], bh[p][hh * 2], bh[p][hh * 2 + 1]);
                    }
        }
    }

    const int gid = lane >> 2;
    const int qid = lane & 3;
#pragma unroll
    for (int mt = 0; mt < 2; mt++) {
        int r0 = m0 + wm * 32 + mt * 16 + gid;
#pragma unroll
        for (int nt = 0; nt < 8; nt++) {
            int c = n0 + wn * 64 + nt * 8 + qid * 2;
            if (C) {
                float b0 = 0.f, b1 = 0.f;
                if (bias) { b0 = bias[c]; b1 = bias[c + 1]; }
                *(float2*)&C[(size_t)r0 * N + c] =
                    make_float2(acc[mt][nt][0] + b0, acc[mt][nt][1] + b1);
                *(float2*)&C[(size_t)(r0 + 8) * N + c] =
                    make_float2(acc[mt][nt][2] + b0, acc[mt][nt][3] + b1);
            } else {
                uint32_t hi, lo;
                split2h(acc[mt][nt][0], acc[mt][nt][1], hi, lo);
                *(uint32_t*)&Ch[(size_t)r0 * N + c] = hi;
                *(uint32_t*)&Cl[(size_t)r0 * N + c] = lo;
                split2h(acc[mt][nt][2], acc[mt][nt][3], hi, lo);
                *(uint32_t*)&Ch[(size_t)(r0 + 8) * N + c] = hi;
                *(uint32_t*)&Cl[(size_t)(r0 + 8) * N + c] = lo;
            }
        }
    }
}

// ---------------------------------------------------------------------------
// Tensor-core windowed MQA flash attention (64 q rows, 128 thr, 3 CTAs/SM).
// S 3-product fp16; PV SINGLE product (P fp16, V hi).  KV double-buffered.
// ---------------------------------------------------------------------------
#define AROWB 144
#define ATN_ARR   (64 * AROWB)
#define ATN_SQH   0
#define ATN_SQL   ATN_ARR
#define ATN_STG   (2 * ATN_ARR)
#define ATN_STGSZ (3 * ATN_ARR)       // Kh | Kl | Vh
#define ATN_SMEM  (ATN_STG + 2 * ATN_STGSZ)   // 73728 B -> 3 CTAs/SM

__global__ __launch_bounds__(128, 3)
void attn_mma() {
    extern __shared__ char smc[];
    uint32_t sb = smem_u32(smc);
    const int qt = blockIdx.x, h = blockIdx.y, b = blockIdx.z;
    const int tid = threadIdx.x, lane = tid & 31, w = tid >> 5;
    const int g = lane >> 2, qd = lane & 3;
    const int r8 = lane & 7;

    {
        const char* srcH = (const char*)g_Qh + (size_t)(b * SEQ + qt * 64) * 2304 + h * 128;
        const char* srcL = (const char*)g_Ql + (size_t)(b * SEQ + qt * 64) * 2304 + h * 128;
#pragma unroll
        for (int j = 0; j < 4; j++) {
            int lin = j * 128 + tid, row = lin >> 3, ch = lin & 7;
            CP_ASYNC16(sb + ATN_SQH + row * AROWB + ch * 16,
                       srcH + (size_t)row * 2304 + ch * 16);
            CP_ASYNC16(sb + ATN_SQL + row * AROWB + ch * 16,
                       srcL + (size_t)row * 2304 + ch * 16);
        }
    }

    auto load_kv = [&](int s, int kt) {
        size_t kb = (size_t)(b * SEQ + kt * 64) * 2304;
        uint32_t st = sb + ATN_STG + s * ATN_STGSZ;
#pragma unroll
        for (int j = 0; j < 12; j++) {
            int arr = j >> 2, lin = (j & 3) * 128 + tid;
            int row = lin >> 3, ch = lin & 7;
            const char* base = (arr == 0) ? (const char*)g_Qh + 2048
                             : (arr == 1) ? (const char*)g_Ql + 2048
                                          : (const char*)g_Qh + 2176;
            CP_ASYNC16(st + arr * ATN_ARR + row * AROWB + ch * 16,
                       base + kb + (size_t)row * 2304 + ch * 16);
        }
    };

    int ktlo = qt - 4; if (ktlo < 0) ktlo = 0;
    int kthi = qt + 4; if (kthi > SEQ / 64 - 1) kthi = SEQ / 64 - 1;

    load_kv(0, ktlo); CP_COMMIT();
    if (ktlo < kthi) { load_kv(1, ktlo + 1); CP_COMMIT(); }

    uint32_t qh[4][4], ql[4][4];
    float oacc[8][4];
#pragma unroll
    for (int i = 0; i < 8; i++)
#pragma unroll
        for (int j = 0; j < 4; j++) oacc[i][j] = 0.f;
    float m0 = -1e30f, m1 = -1e30f, l0 = 0.f, l1 = 0.f;

    for (int kt = ktlo; kt <= kthi; kt++) {
        int s = (kt - ktlo) & 1;
        if (kt < kthi) CP_WAIT1(); else CP_WAIT0();
        __syncthreads();

        if (kt == ktlo) {
#pragma unroll
            for (int ks = 0; ks < 4; ks++) {
                uint32_t off = (uint32_t)((w * 16 + (lane & 15)) * AROWB +
                                          ks * 32 + (lane >> 4) * 16);
                LDSM_X4(qh[ks][0], qh[ks][1], qh[ks][2], qh[ks][3], sb + ATN_SQH + off);
                LDSM_X4(ql[ks][0], ql[ks][1], ql[ks][2], ql[ks][3], sb + ATN_SQL + off);
            }
        }

        uint32_t stg = sb + ATN_STG + s * ATN_STGSZ;
        uint32_t pKh = stg, pKl = stg + ATN_ARR;
        uint32_t pVh = stg + 2 * ATN_ARR;

        float sacc[8][4];
#pragma unroll
        for (int i = 0; i < 8; i++)
#pragma unroll
            for (int j = 0; j < 4; j++) sacc[i][j] = 0.f;

#pragma unroll
        for (int ks = 0; ks < 4; ks++)
#pragma unroll
            for (int sg = 0; sg < 4; sg++) {
                uint32_t off = (uint32_t)((sg * 16 + ((lane >> 4) & 1) * 8 + r8) * AROWB +
                                          ks * 32 + ((lane >> 3) & 1) * 16);
                uint32_t kh0, kh1, kh2, kh3, kl0, kl1, kl2, kl3;
                LDSM_X4(kh0, kh1, kh2, kh3, pKh + off);
                LDSM_X4(kl0, kl1, kl2, kl3, pKl + off);
                mma16816(sacc[sg * 2],     qh[ks], kh0, kh1);
                mma16816(sacc[sg * 2],     qh[ks], kl0, kl1);
                mma16816(sacc[sg * 2],     ql[ks], kh0, kh1);
                mma16816(sacc[sg * 2 + 1], qh[ks], kh2, kh3);
                mma16816(sacc[sg * 2 + 1], qh[ks], kl2, kl3);
                mma16816(sacc[sg * 2 + 1], ql[ks], kh2, kh3);
            }

        int rel = kt - qt;
#pragma unroll
        for (int nt = 0; nt < 8; nt++)
#pragma unroll
            for (int e = 0; e < 4; e++) sacc[nt][e] *= 0.125f;
        if (rel == 4 || rel == -4) {
#pragma unroll
            for (int nt = 0; nt < 8; nt++)
#pragma unroll
                for (int e = 0; e < 4; e++) {
                    int ri = w * 16 + g + ((e >= 2) ? 8 : 0);
                    int cj = nt * 8 + 2 * qd + (e & 1);
                    bool ok = (rel == 4) ? (cj <= ri) : (cj >= ri);
                    if (!ok) sacc[nt][e] = -1e30f;
                }
        }

        float rm0 = -1e30f, rm1 = -1e30f;
#pragma unroll
        for (int nt = 0; nt < 8; nt++) {
            rm0 = fmaxf(rm0, fmaxf(sacc[nt][0], sacc[nt][1]));
            rm1 = fmaxf(rm1, fmaxf(sacc[nt][2], sacc[nt][3]));
        }
        rm0 = fmaxf(rm0, __shfl_xor_sync(0xffffffffu, rm0, 1));
        rm0 = fmaxf(rm0, __shfl_xor_sync(0xffffffffu, rm0, 2));
        rm1 = fmaxf(rm1, __shfl_xor_sync(0xffffffffu, rm1, 1));
        rm1 = fmaxf(rm1, __shfl_xor_sync(0xffffffffu, rm1, 2));
        float nm0 = fmaxf(m0, rm0), nm1 = fmaxf(m1, rm1);
        float c0 = __expf(m0 - nm0), c1 = __expf(m1 - nm1);
        m0 = nm0; m1 = nm1;

        float sum0 = 0.f, sum1 = 0.f;
#pragma unroll
        for (int nt = 0; nt < 8; nt++) {
            sacc[nt][0] = __expf(sacc[nt][0] - nm0);
            sacc[nt][1] = __expf(sacc[nt][1] - nm0);
            sacc[nt][2] = __expf(sacc[nt][2] - nm1);
            sacc[nt][3] = __expf(sacc[nt][3] - nm1);
            sum0 += sacc[nt][0] + sacc[nt][1];
            sum1 += sacc[nt][2] + sacc[nt][3];
        }
        sum0 += __shfl_xor_sync(0xffffffffu, sum0, 1);
        sum0 += __shfl_xor_sync(0xffffffffu, sum0, 2);
        sum1 += __shfl_xor_sync(0xffffffffu, sum1, 1);
        sum1 += __shfl_xor_sync(0xffffffffu, sum1, 2);
        l0 = l0 * c0 + sum0; l1 = l1 * c1 + sum1;
#pragma unroll
        for (int nt = 0; nt < 8; nt++) {
            oacc[nt][0] *= c0; oacc[nt][1] *= c0;
            oacc[nt][2] *= c1; oacc[nt][3] *= c1;
        }

        // ---- P frags (fp16, single product) ----
        uint32_t ph[4][4];
#pragma unroll
        for (int kg = 0; kg < 4; kg++) {
            ph[kg][0] = pack2h(sacc[2 * kg][0],     sacc[2 * kg][1]);
            ph[kg][1] = pack2h(sacc[2 * kg][2],     sacc[2 * kg][3]);
            ph[kg][2] = pack2h(sacc[2 * kg + 1][0], sacc[2 * kg + 1][1]);
            ph[kg][3] = pack2h(sacc[2 * kg + 1][2], sacc[2 * kg + 1][3]);
        }

        // ---- O += P @ V (1 product) ----
#pragma unroll
        for (int kg = 0; kg < 4; kg++)
#pragma unroll
            for (int dg = 0; dg < 4; dg++) {
                uint32_t off = (uint32_t)((kg * 16 + ((lane >> 3) & 1) * 8 + r8) * AROWB +
                                          dg * 32 + ((lane >> 4) & 1) * 16);
                uint32_t vh0, vh1, vh2, vh3;
                LDSM_X4T(vh0, vh1, vh2, vh3, pVh + off);
                mma16816(oacc[dg * 2],     ph[kg], vh0, vh1);
                mma16816(oacc[dg * 2 + 1], ph[kg], vh2, vh3);
            }

        __syncthreads();
        if (kt + 2 <= kthi) { load_kv(s, kt + 2); CP_COMMIT(); }
    }

    float inv0 = 1.0f / l0, inv1 = 1.0f / l1;
    size_t row0 = (size_t)(b * SEQ + qt * 64 + w * 16 + g);
    size_t row1 = row0 + 8;
#pragma unroll
    for (int nt = 0; nt < 8; nt++) {
        int col = h * 64 + nt * 8 + 2 * qd;
        uint32_t hi, lo;
        split2h(oacc[nt][0] * inv0, oacc[nt][1] * inv0, hi, lo);
        *(uint32_t*)&g_Oh[row0 * WIDTH + col] = hi;
        *(uint32_t*)&g_Ol[row0 * WIDTH + col] = lo;
        split2h(oacc[nt][2] * inv1, oacc[nt][3] * inv1, hi, lo);
        *(uint32_t*)&g_Oh[row1 * WIDTH + col] = hi;
        *(uint32_t*)&g_Ol[row1 * WIDTH + col] = lo;
    }
}

// ---------------------------------------------------------------------------
// Launch
// ---------------------------------------------------------------------------
extern "C" void kernel_launch(void* const* d_in, const int* in_sizes, int n_in,
                              void* d_out, int out_size) {
    const float* x  = (const float*)d_in[0];
    const float* Wq = (const float*)d_in[1];
    const float* Wk = (const float*)d_in[2];
    const float* Wv = (const float*)d_in[3];
    const float* Wf = (const float*)d_in[4];
    const float* bf = (const float*)d_in[5];
    float* out = (float*)d_out;
    (void)in_sizes; (void)n_in; (void)out_size;

    __half *pAh, *pAl, *pWh, *pFh, *pQh, *pQl, *pOh, *pOl;
    cudaGetSymbolAddress((void**)&pAh, g_Ah);
    cudaGetSymbolAddress((void**)&pAl, g_Al);
    cudaGetSymbolAddress((void**)&pWh, g_Wh);
    cudaGetSymbolAddress((void**)&pFh, g_Fh);
    cudaGetSymbolAddress((void**)&pQh, g_Qh);
    cudaGetSymbolAddress((void**)&pQl, g_Ql);
    cudaGetSymbolAddress((void**)&pOh, g_Oh);
    cudaGetSymbolAddress((void**)&pOl, g_Ol);

    cudaFuncSetAttribute(mmagemm,
                         cudaFuncAttributeMaxDynamicSharedMemorySize, GEMM_SMEM);
    cudaFuncSetAttribute(attn_mma,
                         cudaFuncAttributeMaxDynamicSharedMemorySize, ATN_SMEM);

    // fused conversions (x hi/lo, packed W hi, Wf hi)
    convert_all<<<(NALLQ + 255) / 256, 256>>>(x, Wq, Wk, Wv, Wf);

    // QKV projection -> fp16 hi/lo qkv
    mmagemm<<<dim3(NQKV / 128, TOK / 128), 256, GEMM_SMEM>>>(
        pAh, pAl, pWh, nullptr, pQh, pQl, TOK, NQKV, WIDTH, nullptr);

    // tensor-core windowed attention -> fp16 hi/lo O
    attn_mma<<<dim3(SEQ / 64, NH, BATCH), 128, ATN_SMEM>>>();

    // output projection + bias -> fp32 out
    mmagemm<<<dim3(WIDTH / 128, TOK / 128), 256, GEMM_SMEM>>>(
        pOh, pOl, pFh, out, nullptr, nullptr, TOK, WIDTH, WIDTH, bf);
}

// round 12
// speedup vs baseline: 1.2369x; 1.0734x over previous
#include <cuda_runtime.h>
#include <cuda_fp16.h>
#include <cstdint>
#include <math.h>

// Problem constants
#define SEQ    2048
#define BATCH  2
#define WIDTH  1024
#define NH     16
#define HD     64
#define WIN    256
#define TOK    (BATCH*SEQ)     // 4096
#define NQKV   1152            // 1024 q + 64 k + 64 v

// ---------------------------------------------------------------------------
// Scratch (device globals).
// ---------------------------------------------------------------------------
__device__ __half g_Ah[TOK * WIDTH],  g_Al[TOK * WIDTH];    // x hi/lo
__device__ __half g_Wh[NQKV * WIDTH];                        // [Wq;Wk;Wv] hi
__device__ __half g_Fh[WIDTH * WIDTH];                       // Wf hi
__device__ __half g_Qh[TOK * NQKV],  g_Ql[TOK * NQKV];       // qkv hi/lo
__device__ __half g_Oh[TOK * WIDTH];                         // attn out fp16

// ---------------------------------------------------------------------------
// Helpers
// ---------------------------------------------------------------------------
__device__ __forceinline__ uint32_t smem_u32(const void* p) {
    uint32_t a;
    asm("{ .reg .u64 t; cvta.to.shared.u64 t, %1; cvt.u32.u64 %0, t; }"
        : "=r"(a) : "l"(p));
    return a;
}

#define CP_ASYNC16(sa, ga) \
    asm volatile("cp.async.cg.shared.global [%0], [%1], 16;" :: "r"(sa), "l"(ga))
#define CP_COMMIT() asm volatile("cp.async.commit_group;" ::: "memory")
#define CP_WAIT1()  asm volatile("cp.async.wait_group 1;" ::: "memory")
#define CP_WAIT0()  asm volatile("cp.async.wait_group 0;" ::: "memory")

#define LDSM_X4(r0, r1, r2, r3, addr) \
    asm volatile("ldmatrix.sync.aligned.m8n8.x4.shared.b16 {%0,%1,%2,%3}, [%4];" \
        : "=r"(r0), "=r"(r1), "=r"(r2), "=r"(r3) : "r"(addr))
#define LDSM_X4T(r0, r1, r2, r3, addr) \
    asm volatile("ldmatrix.sync.aligned.m8n8.x4.trans.shared.b16 {%0,%1,%2,%3}, [%4];" \
        : "=r"(r0), "=r"(r1), "=r"(r2), "=r"(r3) : "r"(addr))

__device__ __forceinline__ void mma16816(float* c, const uint32_t* a,
                                         uint32_t b0, uint32_t b1) {
    asm volatile(
        "mma.sync.aligned.m16n8k16.row.col.f32.f16.f16.f32 "
        "{%0,%1,%2,%3}, {%4,%5,%6,%7}, {%8,%9}, {%0,%1,%2,%3};"
        : "+f"(c[0]), "+f"(c[1]), "+f"(c[2]), "+f"(c[3])
        : "r"(a[0]), "r"(a[1]), "r"(a[2]), "r"(a[3]), "r"(b0), "r"(b1));
}

__device__ __forceinline__ uint32_t packh(__half a, __half b) {
    __half2 t; t.x = a; t.y = b;
    return *(uint32_t*)&t;
}
__device__ __forceinline__ uint32_t pack2h(float a, float b) {
    return packh(__float2half_rn(a), __float2half_rn(b));
}
__device__ __forceinline__ void split2h(float a, float b, uint32_t& hi, uint32_t& lo) {
    __half ah = __float2half_rn(a), bh = __float2half_rn(b);
    hi = packh(ah, bh);
    lo = packh(__float2half_rn(a - __half2float(ah)),
               __float2half_rn(b - __half2float(bh)));
}
__device__ __forceinline__ void split_h(float v, __half& h, __half& l) {
    h = __float2half_rn(v);
    l = __float2half_rn(v - __half2float(h));
}

// ---------------------------------------------------------------------------
// One fused conversion kernel: x -> Ah/Al ; [Wq;Wk;Wv] -> Wh ; Wf -> Fh.
// ---------------------------------------------------------------------------
#define NXQ (TOK * WIDTH / 4)
#define NWQ (NQKV * WIDTH / 4)
#define NFQ (WIDTH * WIDTH / 4)
#define NALLQ (NXQ + NWQ + NFQ)

__global__ void convert_all(const float* __restrict__ x,
                            const float* __restrict__ Wq,
                            const float* __restrict__ Wk,
                            const float* __restrict__ Wv,
                            const float* __restrict__ Wf) {
    int q = blockIdx.x * blockDim.x + threadIdx.x;
    if (q < NXQ) {
        int i = q * 4;
        float4 v = *(const float4*)(x + i);
        __half h0, h1, h2, h3, l0, l1, l2, l3;
        split_h(v.x, h0, l0); split_h(v.y, h1, l1);
        split_h(v.z, h2, l2); split_h(v.w, h3, l3);
        __half2* H = (__half2*)(g_Ah + i);
        __half2* L = (__half2*)(g_Al + i);
        H[0] = __half2(h0, h1); H[1] = __half2(h2, h3);
        L[0] = __half2(l0, l1); L[1] = __half2(l2, l3);
    } else if (q < NXQ + NWQ) {
        int e = (q - NXQ) * 4;
        int row = e >> 10, c = e & 1023;
        const float* src;
        if (row < 1024)      src = Wq + (size_t)row * WIDTH + c;
        else if (row < 1088) src = Wk + (size_t)(row - 1024) * WIDTH + c;
        else                 src = Wv + (size_t)(row - 1088) * WIDTH + c;
        float4 v = *(const float4*)src;
        __half2* H = (__half2*)(g_Wh + e);
        H[0] = __half2(__float2half_rn(v.x), __float2half_rn(v.y));
        H[1] = __half2(__float2half_rn(v.z), __float2half_rn(v.w));
    } else if (q < NALLQ) {
        int i = (q - NXQ - NWQ) * 4;
        float4 v = *(const float4*)(Wf + i);
        __half2* H = (__half2*)(g_Fh + i);
        H[0] = __half2(__float2half_rn(v.x), __float2half_rn(v.y));
        H[1] = __half2(__float2half_rn(v.z), __float2half_rn(v.w));
    }
}

// ---------------------------------------------------------------------------
// mma.sync GEMM: C = A @ B^T (+bias).  A = Ah [+ Al if non-null], B = Bh.
// 128x128x32 tile, 8 warps as 4(M)x2(N), 3-stage cp.async, single barrier,
// 2 CTAs/SM.
// ---------------------------------------------------------------------------
#define BK 32
#define ROWB 80
#define ARR_B (128 * ROWB)            // 10240 B
#define STAGE_B (3 * ARR_B)           // Ah | Al | Bh = 30720 B
#define GEMM_SMEM (3 * STAGE_B)       // 92160 B -> 2 CTAs/SM

__global__ __launch_bounds__(256, 2)
void mmagemm(const __half* __restrict__ Ah, const __half* __restrict__ Al,
             const __half* __restrict__ Bh,
             float* __restrict__ C,
             __half* __restrict__ Ch, __half* __restrict__ Cl,
             int M, int N, int K, const float* __restrict__ bias) {
    extern __shared__ char smem[];
    uint32_t sb = smem_u32(smem);
    const int tid  = threadIdx.x;
    const int lane = tid & 31;
    const int wid  = tid >> 5;
    const int wm   = wid & 3;
    const int wn   = wid >> 2;
    const int m0 = blockIdx.y * 128;
    const int n0 = blockIdx.x * 128;
    const int NK = K / BK;
    const size_t RS = (size_t)K * 2;
    const bool useAl = (Al != nullptr);

    const int crow = tid >> 1;
    const int ccol = (tid & 1) * 2;
    const uint32_t s_off0 = crow * ROWB + ccol * 16;
    const char* gA0 = (const char*)Ah + (size_t)(m0 + crow) * RS + ccol * 16;
    const char* gA1 = useAl ? (const char*)Al + (size_t)(m0 + crow) * RS + ccol * 16
                            : nullptr;
    const char* gB0 = (const char*)Bh + (size_t)(n0 + crow) * RS + ccol * 16;

    auto load_stage = [&](int s, int it) {
        uint32_t st = sb + s * STAGE_B;
        size_t kb = (size_t)it * (BK * 2);
        CP_ASYNC16(st + 0 * ARR_B + s_off0,      gA0 + kb);
        CP_ASYNC16(st + 0 * ARR_B + s_off0 + 16, gA0 + kb + 16);
        if (useAl) {
            CP_ASYNC16(st + 1 * ARR_B + s_off0,      gA1 + kb);
            CP_ASYNC16(st + 1 * ARR_B + s_off0 + 16, gA1 + kb + 16);
        }
        CP_ASYNC16(st + 2 * ARR_B + s_off0,      gB0 + kb);
        CP_ASYNC16(st + 2 * ARR_B + s_off0 + 16, gB0 + kb + 16);
    };

    float acc[2][8][4];
#pragma unroll
    for (int i = 0; i < 2; i++)
#pragma unroll
        for (int j = 0; j < 8; j++)
#pragma unroll
            for (int q = 0; q < 4; q++) acc[i][j][q] = 0.f;

    const int asub = lane >> 3;
    const int a_row_in = (lane & 7) + 8 * (asub & 1);
    const int a_chunk  = asub >> 1;
    const int b_row_in = (lane & 7) + 8 * (asub >> 1);
    const int b_chunk  = asub & 1;

    load_stage(0, 0); CP_COMMIT();
    load_stage(1, 1); CP_COMMIT();

    for (int it = 0; it < NK; ++it) {
        if (it + 1 < NK) CP_WAIT1(); else CP_WAIT0();
        __syncthreads();
        if (it + 2 < NK) { load_stage((it + 2) % 3, it + 2); CP_COMMIT(); }

        uint32_t st  = sb + (it % 3) * STAGE_B;
        uint32_t pAh = st;
        uint32_t pAl = st + ARR_B;
        uint32_t pBh = st + 2 * ARR_B;

#pragma unroll
        for (int kk = 0; kk < 2; kk++) {
            uint32_t ah[2][4], al[2][4], bh[4][4];
#pragma unroll
            for (int mt = 0; mt < 2; mt++) {
                uint32_t off = (uint32_t)((wm * 32 + mt * 16 + a_row_in) * ROWB +
                                          (kk * 2 + a_chunk) * 16);
                LDSM_X4(ah[mt][0], ah[mt][1], ah[mt][2], ah[mt][3], pAh + off);
                if (useAl)
                    LDSM_X4(al[mt][0], al[mt][1], al[mt][2], al[mt][3], pAl + off);
            }
#pragma unroll
            for (int p = 0; p < 4; p++) {
                uint32_t off = (uint32_t)((wn * 64 + p * 16 + b_row_in) * ROWB +
                                          (kk * 2 + b_chunk) * 16);
                LDSM_X4(bh[p][0], bh[p][1], bh[p][2], bh[p][3], pBh + off);
            }
#pragma unroll
            for (int mt = 0; mt < 2; mt++)
#pragma unroll
                for (int p = 0; p < 4; p++)
#pragma unroll
                    for (int hh = 0; hh < 2; hh++) {
                        int nt = p * 2 + hh;
                        mma16816(acc[mt][nt], ah[mt], bh[p][hh * 2], bh[p][hh * 2 + 1]);
                        if (useAl)
                            mma16816(acc[mt][nt], al[mt], bh[p][hh * 2], bh[p][hh * 2 + 1]);
                    }
        }
    }

    const int gid = lane >> 2;
    const int qid = lane & 3;
#pragma unroll
    for (int mt = 0; mt < 2; mt++) {
        int r0 = m0 + wm * 32 + mt * 16 + gid;
#pragma unroll
        for (int nt = 0; nt < 8; nt++) {
            int c = n0 + wn * 64 + nt * 8 + qid * 2;
            if (C) {
                float b0 = 0.f, b1 = 0.f;
                if (bias) { b0 = bias[c]; b1 = bias[c + 1]; }
                *(float2*)&C[(size_t)r0 * N + c] =
                    make_float2(acc[mt][nt][0] + b0, acc[mt][nt][1] + b1);
                *(float2*)&C[(size_t)(r0 + 8) * N + c] =
                    make_float2(acc[mt][nt][2] + b0, acc[mt][nt][3] + b1);
            } else {
                uint32_t hi, lo;
                split2h(acc[mt][nt][0], acc[mt][nt][1], hi, lo);
                *(uint32_t*)&Ch[(size_t)r0 * N + c] = hi;
                *(uint32_t*)&Cl[(size_t)r0 * N + c] = lo;
                split2h(acc[mt][nt][2], acc[mt][nt][3], hi, lo);
                *(uint32_t*)&Ch[(size_t)(r0 + 8) * N + c] = hi;
                *(uint32_t*)&Cl[(size_t)(r0 + 8) * N + c] = lo;
            }
        }
    }
}

// ---------------------------------------------------------------------------
// Tensor-core windowed MQA flash attention (64 q rows, 128 thr, 3 CTAs/SM).
// S 3-product fp16; PV single product; output fp16 (single array).
// ---------------------------------------------------------------------------
#define AROWB 144
#define ATN_ARR   (64 * AROWB)
#define ATN_SQH   0
#define ATN_SQL   ATN_ARR
#define ATN_STG   (2 * ATN_ARR)
#define ATN_STGSZ (3 * ATN_ARR)       // Kh | Kl | Vh
#define ATN_SMEM  (ATN_STG + 2 * ATN_STGSZ)   // 73728 B -> 3 CTAs/SM

__global__ __launch_bounds__(128, 3)
void attn_mma() {
    extern __shared__ char smc[];
    uint32_t sb = smem_u32(smc);
    const int qt = blockIdx.x, h = blockIdx.y, b = blockIdx.z;
    const int tid = threadIdx.x, lane = tid & 31, w = tid >> 5;
    const int g = lane >> 2, qd = lane & 3;
    const int r8 = lane & 7;

    {
        const char* srcH = (const char*)g_Qh + (size_t)(b * SEQ + qt * 64) * 2304 + h * 128;
        const char* srcL = (const char*)g_Ql + (size_t)(b * SEQ + qt * 64) * 2304 + h * 128;
#pragma unroll
        for (int j = 0; j < 4; j++) {
            int lin = j * 128 + tid, row = lin >> 3, ch = lin & 7;
            CP_ASYNC16(sb + ATN_SQH + row * AROWB + ch * 16,
                       srcH + (size_t)row * 2304 + ch * 16);
            CP_ASYNC16(sb + ATN_SQL + row * AROWB + ch * 16,
                       srcL + (size_t)row * 2304 + ch * 16);
        }
    }

    auto load_kv = [&](int s, int kt) {
        size_t kb = (size_t)(b * SEQ + kt * 64) * 2304;
        uint32_t st = sb + ATN_STG + s * ATN_STGSZ;
#pragma unroll
        for (int j = 0; j < 12; j++) {
            int arr = j >> 2, lin = (j & 3) * 128 + tid;
            int row = lin >> 3, ch = lin & 7;
            const char* base = (arr == 0) ? (const char*)g_Qh + 2048
                             : (arr == 1) ? (const char*)g_Ql + 2048
                                          : (const char*)g_Qh + 2176;
            CP_ASYNC16(st + arr * ATN_ARR + row * AROWB + ch * 16,
                       base + kb + (size_t)row * 2304 + ch * 16);
        }
    };

    int ktlo = qt - 4; if (ktlo < 0) ktlo = 0;
    int kthi = qt + 4; if (kthi > SEQ / 64 - 1) kthi = SEQ / 64 - 1;

    load_kv(0, ktlo); CP_COMMIT();
    if (ktlo < kthi) { load_kv(1, ktlo + 1); CP_COMMIT(); }

    uint32_t qh[4][4], ql[4][4];
    float oacc[8][4];
#pragma unroll
    for (int i = 0; i < 8; i++)
#pragma unroll
        for (int j = 0; j < 4; j++) oacc[i][j] = 0.f;
    float m0 = -1e30f, m1 = -1e30f, l0 = 0.f, l1 = 0.f;

    for (int kt = ktlo; kt <= kthi; kt++) {
        int s = (kt - ktlo) & 1;
        if (kt < kthi) CP_WAIT1(); else CP_WAIT0();
        __syncthreads();

        if (kt == ktlo) {
#pragma unroll
            for (int ks = 0; ks < 4; ks++) {
                uint32_t off = (uint32_t)((w * 16 + (lane & 15)) * AROWB +
                                          ks * 32 + (lane >> 4) * 16);
                LDSM_X4(qh[ks][0], qh[ks][1], qh[ks][2], qh[ks][3], sb + ATN_SQH + off);
                LDSM_X4(ql[ks][0], ql[ks][1], ql[ks][2], ql[ks][3], sb + ATN_SQL + off);
            }
        }

        uint32_t stg = sb + ATN_STG + s * ATN_STGSZ;
        uint32_t pKh = stg, pKl = stg + ATN_ARR;
        uint32_t pVh = stg + 2 * ATN_ARR;

        float sacc[8][4];
#pragma unroll
        for (int i = 0; i < 8; i++)
#pragma unroll
            for (int j = 0; j < 4; j++) sacc[i][j] = 0.f;

#pragma unroll
        for (int ks = 0; ks < 4; ks++)
#pragma unroll
            for (int sg = 0; sg < 4; sg++) {
                uint32_t off = (uint32_t)((sg * 16 + ((lane >> 4) & 1) * 8 + r8) * AROWB +
                                          ks * 32 + ((lane >> 3) & 1) * 16);
                uint32_t kh0, kh1, kh2, kh3, kl0, kl1, kl2, kl3;
                LDSM_X4(kh0, kh1, kh2, kh3, pKh + off);
                LDSM_X4(kl0, kl1, kl2, kl3, pKl + off);
                mma16816(sacc[sg * 2],     qh[ks], kh0, kh1);
                mma16816(sacc[sg * 2],     qh[ks], kl0, kl1);
                mma16816(sacc[sg * 2],     ql[ks], kh0, kh1);
                mma16816(sacc[sg * 2 + 1], qh[ks], kh2, kh3);
                mma16816(sacc[sg * 2 + 1], qh[ks], kl2, kl3);
                mma16816(sacc[sg * 2 + 1], ql[ks], kh2, kh3);
            }

        int rel = kt - qt;
#pragma unroll
        for (int nt = 0; nt < 8; nt++)
#pragma unroll
            for (int e = 0; e < 4; e++) sacc[nt][e] *= 0.125f;
        if (rel == 4 || rel == -4) {
#pragma unroll
            for (int nt = 0; nt < 8; nt++)
#pragma unroll
                for (int e = 0; e < 4; e++) {
                    int ri = w * 16 + g + ((e >= 2) ? 8 : 0);
                    int cj = nt * 8 + 2 * qd + (e & 1);
                    bool ok = (rel == 4) ? (cj <= ri) : (cj >= ri);
                    if (!ok) sacc[nt][e] = -1e30f;
                }
        }

        float rm0 = -1e30f, rm1 = -1e30f;
#pragma unroll
        for (int nt = 0; nt < 8; nt++) {
            rm0 = fmaxf(rm0, fmaxf(sacc[nt][0], sacc[nt][1]));
            rm1 = fmaxf(rm1, fmaxf(sacc[nt][2], sacc[nt][3]));
        }
        rm0 = fmaxf(rm0, __shfl_xor_sync(0xffffffffu, rm0, 1));
        rm0 = fmaxf(rm0, __shfl_xor_sync(0xffffffffu, rm0, 2));
        rm1 = fmaxf(rm1, __shfl_xor_sync(0xffffffffu, rm1, 1));
        rm1 = fmaxf(rm1, __shfl_xor_sync(0xffffffffu, rm1, 2));
        float nm0 = fmaxf(m0, rm0), nm1 = fmaxf(m1, rm1);
        float c0 = __expf(m0 - nm0), c1 = __expf(m1 - nm1);
        m0 = nm0; m1 = nm1;

        float sum0 = 0.f, sum1 = 0.f;
#pragma unroll
        for (int nt = 0; nt < 8; nt++) {
            sacc[nt][0] = __expf(sacc[nt][0] - nm0);
            sacc[nt][1] = __expf(sacc[nt][1] - nm0);
            sacc[nt][2] = __expf(sacc[nt][2] - nm1);
            sacc[nt][3] = __expf(sacc[nt][3] - nm1);
            sum0 += sacc[nt][0] + sacc[nt][1];
            sum1 += sacc[nt][2] + sacc[nt][3];
        }
        sum0 += __shfl_xor_sync(0xffffffffu, sum0, 1);
        sum0 += __shfl_xor_sync(0xffffffffu, sum0, 2);
        sum1 += __shfl_xor_sync(0xffffffffu, sum1, 1);
        sum1 += __shfl_xor_sync(0xffffffffu, sum1, 2);
        l0 = l0 * c0 + sum0; l1 = l1 * c1 + sum1;
#pragma unroll
        for (int nt = 0; nt < 8; nt++) {
            oacc[nt][0] *= c0; oacc[nt][1] *= c0;
            oacc[nt][2] *= c1; oacc[nt][3] *= c1;
        }

        uint32_t ph[4][4];
#pragma unroll
        for (int kg = 0; kg < 4; kg++) {
            ph[kg][0] = pack2h(sacc[2 * kg][0],     sacc[2 * kg][1]);
            ph[kg][1] = pack2h(sacc[2 * kg][2],     sacc[2 * kg][3]);
            ph[kg][2] = pack2h(sacc[2 * kg + 1][0], sacc[2 * kg + 1][1]);
            ph[kg][3] = pack2h(sacc[2 * kg + 1][2], sacc[2 * kg + 1][3]);
        }

#pragma unroll
        for (int kg = 0; kg < 4; kg++)
#pragma unroll
            for (int dg = 0; dg < 4; dg++) {
                uint32_t off = (uint32_t)((kg * 16 + ((lane >> 3) & 1) * 8 + r8) * AROWB +
                                          dg * 32 + ((lane >> 4) & 1) * 16);
                uint32_t vh0, vh1, vh2, vh3;
                LDSM_X4T(vh0, vh1, vh2, vh3, pVh + off);
                mma16816(oacc[dg * 2],     ph[kg], vh0, vh1);
                mma16816(oacc[dg * 2 + 1], ph[kg], vh2, vh3);
            }

        __syncthreads();
        if (kt + 2 <= kthi) { load_kv(s, kt + 2); CP_COMMIT(); }
    }

    // finalize: /l, store fp16 only
    float inv0 = 1.0f / l0, inv1 = 1.0f / l1;
    size_t row0 = (size_t)(b * SEQ + qt * 64 + w * 16 + g);
    size_t row1 = row0 + 8;
#pragma unroll
    for (int nt = 0; nt < 8; nt++) {
        int col = h * 64 + nt * 8 + 2 * qd;
        *(uint32_t*)&g_Oh[row0 * WIDTH + col] =
            pack2h(oacc[nt][0] * inv0, oacc[nt][1] * inv0);
        *(uint32_t*)&g_Oh[row1 * WIDTH + col] =
            pack2h(oacc[nt][2] * inv1, oacc[nt][3] * inv1);
    }
}

// ---------------------------------------------------------------------------
// Launch
// ---------------------------------------------------------------------------
extern "C" void kernel_launch(void* const* d_in, const int* in_sizes, int n_in,
                              void* d_out, int out_size) {
    const float* x  = (const float*)d_in[0];
    const float* Wq = (const float*)d_in[1];
    const float* Wk = (const float*)d_in[2];
    const float* Wv = (const float*)d_in[3];
    const float* Wf = (const float*)d_in[4];
    const float* bf = (const float*)d_in[5];
    float* out = (float*)d_out;
    (void)in_sizes; (void)n_in; (void)out_size;

    __half *pAh, *pAl, *pWh, *pFh, *pQh, *pQl, *pOh;
    cudaGetSymbolAddress((void**)&pAh, g_Ah);
    cudaGetSymbolAddress((void**)&pAl, g_Al);
    cudaGetSymbolAddress((void**)&pWh, g_Wh);
    cudaGetSymbolAddress((void**)&pFh, g_Fh);
    cudaGetSymbolAddress((void**)&pQh, g_Qh);
    cudaGetSymbolAddress((void**)&pQl, g_Ql);
    cudaGetSymbolAddress((void**)&pOh, g_Oh);

    cudaFuncSetAttribute(mmagemm,
                         cudaFuncAttributeMaxDynamicSharedMemorySize, GEMM_SMEM);
    cudaFuncSetAttribute(attn_mma,
                         cudaFuncAttributeMaxDynamicSharedMemorySize, ATN_SMEM);

    // fused conversions (x hi/lo, packed W hi, Wf hi)
    convert_all<<<(NALLQ + 255) / 256, 256>>>(x, Wq, Wk, Wv, Wf);

    // QKV projection (2 products) -> fp16 hi/lo qkv
    mmagemm<<<dim3(NQKV / 128, TOK / 128), 256, GEMM_SMEM>>>(
        pAh, pAl, pWh, nullptr, pQh, pQl, TOK, NQKV, WIDTH, nullptr);

    // tensor-core windowed attention -> fp16 O
    attn_mma<<<dim3(SEQ / 64, NH, BATCH), 128, ATN_SMEM>>>();

    // output projection + bias (single product) -> fp32 out
    mmagemm<<<dim3(WIDTH / 128, TOK / 128), 256, GEMM_SMEM>>>(
        pOh, nullptr, pFh, out, nullptr, nullptr, TOK, WIDTH, WIDTH, bf);
}

// round 13
// speedup vs baseline: 1.5690x; 1.2685x over previous
#include <cuda_runtime.h>
#include <cuda_fp16.h>
#include <cstdint>
#include <math.h>

// Problem constants
#define SEQ    2048
#define BATCH  2
#define WIDTH  1024
#define NH     16
#define HD     64
#define WIN    256
#define TOK    (BATCH*SEQ)     // 4096
#define NQKV   1152            // 1024 q + 64 k + 64 v

// ---------------------------------------------------------------------------
// Scratch (device globals).  All operands fp16 (single product per GEMM);
// qkv keeps hi/lo split so S = QK^T stays 3-product accurate.
// ---------------------------------------------------------------------------
__device__ __half g_Ah[TOK * WIDTH];                         // x fp16
__device__ __half g_Wh[NQKV * WIDTH];                        // [Wq;Wk;Wv] fp16
__device__ __half g_Fh[WIDTH * WIDTH];                       // Wf fp16
__device__ __half g_Qh[TOK * NQKV],  g_Ql[TOK * NQKV];       // qkv hi/lo
__device__ __half g_Oh[TOK * WIDTH];                         // attn out fp16

// ---------------------------------------------------------------------------
// Helpers
// ---------------------------------------------------------------------------
__device__ __forceinline__ uint32_t smem_u32(const void* p) {
    uint32_t a;
    asm("{ .reg .u64 t; cvta.to.shared.u64 t, %1; cvt.u32.u64 %0, t; }"
        : "=r"(a) : "l"(p));
    return a;
}

#define CP_ASYNC16(sa, ga) \
    asm volatile("cp.async.cg.shared.global [%0], [%1], 16;" :: "r"(sa), "l"(ga))
#define CP_COMMIT() asm volatile("cp.async.commit_group;" ::: "memory")
#define CP_WAIT1()  asm volatile("cp.async.wait_group 1;" ::: "memory")
#define CP_WAIT0()  asm volatile("cp.async.wait_group 0;" ::: "memory")

#define LDSM_X4(r0, r1, r2, r3, addr) \
    asm volatile("ldmatrix.sync.aligned.m8n8.x4.shared.b16 {%0,%1,%2,%3}, [%4];" \
        : "=r"(r0), "=r"(r1), "=r"(r2), "=r"(r3) : "r"(addr))
#define LDSM_X4T(r0, r1, r2, r3, addr) \
    asm volatile("ldmatrix.sync.aligned.m8n8.x4.trans.shared.b16 {%0,%1,%2,%3}, [%4];" \
        : "=r"(r0), "=r"(r1), "=r"(r2), "=r"(r3) : "r"(addr))

__device__ __forceinline__ void mma16816(float* c, const uint32_t* a,
                                         uint32_t b0, uint32_t b1) {
    asm volatile(
        "mma.sync.aligned.m16n8k16.row.col.f32.f16.f16.f32 "
        "{%0,%1,%2,%3}, {%4,%5,%6,%7}, {%8,%9}, {%0,%1,%2,%3};"
        : "+f"(c[0]), "+f"(c[1]), "+f"(c[2]), "+f"(c[3])
        : "r"(a[0]), "r"(a[1]), "r"(a[2]), "r"(a[3]), "r"(b0), "r"(b1));
}

__device__ __forceinline__ uint32_t packh(__half a, __half b) {
    __half2 t; t.x = a; t.y = b;
    return *(uint32_t*)&t;
}
__device__ __forceinline__ uint32_t pack2h(float a, float b) {
    return packh(__float2half_rn(a), __float2half_rn(b));
}
__device__ __forceinline__ void split2h(float a, float b, uint32_t& hi, uint32_t& lo) {
    __half ah = __float2half_rn(a), bh = __float2half_rn(b);
    hi = packh(ah, bh);
    lo = packh(__float2half_rn(a - __half2float(ah)),
               __float2half_rn(b - __half2float(bh)));
}

// ---------------------------------------------------------------------------
// One fused conversion kernel: x -> Ah ; [Wq;Wk;Wv] -> Wh ; Wf -> Fh.
// ---------------------------------------------------------------------------
#define NXQ (TOK * WIDTH / 4)
#define NWQ (NQKV * WIDTH / 4)
#define NFQ (WIDTH * WIDTH / 4)
#define NALLQ (NXQ + NWQ + NFQ)

__global__ void convert_all(const float* __restrict__ x,
                            const float* __restrict__ Wq,
                            const float* __restrict__ Wk,
                            const float* __restrict__ Wv,
                            const float* __restrict__ Wf) {
    int q = blockIdx.x * blockDim.x + threadIdx.x;
    if (q < NXQ) {
        int i = q * 4;
        float4 v = *(const float4*)(x + i);
        __half2* H = (__half2*)(g_Ah + i);
        H[0] = __half2(__float2half_rn(v.x), __float2half_rn(v.y));
        H[1] = __half2(__float2half_rn(v.z), __float2half_rn(v.w));
    } else if (q < NXQ + NWQ) {
        int e = (q - NXQ) * 4;
        int row = e >> 10, c = e & 1023;
        const float* src;
        if (row < 1024)      src = Wq + (size_t)row * WIDTH + c;
        else if (row < 1088) src = Wk + (size_t)(row - 1024) * WIDTH + c;
        else                 src = Wv + (size_t)(row - 1088) * WIDTH + c;
        float4 v = *(const float4*)src;
        __half2* H = (__half2*)(g_Wh + e);
        H[0] = __half2(__float2half_rn(v.x), __float2half_rn(v.y));
        H[1] = __half2(__float2half_rn(v.z), __float2half_rn(v.w));
    } else if (q < NALLQ) {
        int i = (q - NXQ - NWQ) * 4;
        float4 v = *(const float4*)(Wf + i);
        __half2* H = (__half2*)(g_Fh + i);
        H[0] = __half2(__float2half_rn(v.x), __float2half_rn(v.y));
        H[1] = __half2(__float2half_rn(v.z), __float2half_rn(v.w));
    }
}

// ---------------------------------------------------------------------------
// mma.sync GEMM: C = A @ B^T (+bias), single fp16 product.
// 128x128x32 tile, 8 warps as 4(M)x2(N), 3-stage cp.async, single barrier,
// 2 CTAs/SM.
// ---------------------------------------------------------------------------
#define BK 32
#define ROWB 80
#define ARR_B (128 * ROWB)            // 10240 B
#define STAGE_B (2 * ARR_B)           // Ah | Bh = 20480 B
#define GEMM_SMEM (3 * STAGE_B)       // 61440 B -> 2 CTAs/SM

__global__ __launch_bounds__(256, 2)
void mmagemm(const __half* __restrict__ Ah, const __half* __restrict__ Bh,
             float* __restrict__ C,
             __half* __restrict__ Ch, __half* __restrict__ Cl,
             int M, int N, int K, const float* __restrict__ bias) {
    extern __shared__ char smem[];
    uint32_t sb = smem_u32(smem);
    const int tid  = threadIdx.x;
    const int lane = tid & 31;
    const int wid  = tid >> 5;
    const int wm   = wid & 3;
    const int wn   = wid >> 2;
    const int m0 = blockIdx.y * 128;
    const int n0 = blockIdx.x * 128;
    const int NK = K / BK;
    const size_t RS = (size_t)K * 2;

    const int crow = tid >> 1;
    const int ccol = (tid & 1) * 2;
    const uint32_t s_off0 = crow * ROWB + ccol * 16;
    const char* gA0 = (const char*)Ah + (size_t)(m0 + crow) * RS + ccol * 16;
    const char* gB0 = (const char*)Bh + (size_t)(n0 + crow) * RS + ccol * 16;

    auto load_stage = [&](int s, int it) {
        uint32_t st = sb + s * STAGE_B;
        size_t kb = (size_t)it * (BK * 2);
        CP_ASYNC16(st + 0 * ARR_B + s_off0,      gA0 + kb);
        CP_ASYNC16(st + 0 * ARR_B + s_off0 + 16, gA0 + kb + 16);
        CP_ASYNC16(st + 1 * ARR_B + s_off0,      gB0 + kb);
        CP_ASYNC16(st + 1 * ARR_B + s_off0 + 16, gB0 + kb + 16);
    };

    float acc[2][8][4];
#pragma unroll
    for (int i = 0; i < 2; i++)
#pragma unroll
        for (int j = 0; j < 8; j++)
#pragma unroll
            for (int q = 0; q < 4; q++) acc[i][j][q] = 0.f;

    const int asub = lane >> 3;
    const int a_row_in = (lane & 7) + 8 * (asub & 1);
    const int a_chunk  = asub >> 1;
    const int b_row_in = (lane & 7) + 8 * (asub >> 1);
    const int b_chunk  = asub & 1;

    load_stage(0, 0); CP_COMMIT();
    load_stage(1, 1); CP_COMMIT();

    for (int it = 0; it < NK; ++it) {
        if (it + 1 < NK) CP_WAIT1(); else CP_WAIT0();
        __syncthreads();
        if (it + 2 < NK) { load_stage((it + 2) % 3, it + 2); CP_COMMIT(); }

        uint32_t st  = sb + (it % 3) * STAGE_B;
        uint32_t pAh = st;
        uint32_t pBh = st + ARR_B;

#pragma unroll
        for (int kk = 0; kk < 2; kk++) {
            uint32_t ah[2][4], bh[4][4];
#pragma unroll
            for (int mt = 0; mt < 2; mt++) {
                uint32_t off = (uint32_t)((wm * 32 + mt * 16 + a_row_in) * ROWB +
                                          (kk * 2 + a_chunk) * 16);
                LDSM_X4(ah[mt][0], ah[mt][1], ah[mt][2], ah[mt][3], pAh + off);
            }
#pragma unroll
            for (int p = 0; p < 4; p++) {
                uint32_t off = (uint32_t)((wn * 64 + p * 16 + b_row_in) * ROWB +
                                          (kk * 2 + b_chunk) * 16);
                LDSM_X4(bh[p][0], bh[p][1], bh[p][2], bh[p][3], pBh + off);
            }
#pragma unroll
            for (int mt = 0; mt < 2; mt++)
#pragma unroll
                for (int p = 0; p < 4; p++)
#pragma unroll
                    for (int hh = 0; hh < 2; hh++)
                        mma16816(acc[mt][p * 2 + hh], ah[mt],
                                 bh[p][hh * 2], bh[p][hh * 2 + 1]);
        }
    }

    const int gid = lane >> 2;
    const int qid = lane & 3;
#pragma unroll
    for (int mt = 0; mt < 2; mt++) {
        int r0 = m0 + wm * 32 + mt * 16 + gid;
#pragma unroll
        for (int nt = 0; nt < 8; nt++) {
            int c = n0 + wn * 64 + nt * 8 + qid * 2;
            if (C) {
                float b0 = 0.f, b1 = 0.f;
                if (bias) { b0 = bias[c]; b1 = bias[c + 1]; }
                *(float2*)&C[(size_t)r0 * N + c] =
                    make_float2(acc[mt][nt][0] + b0, acc[mt][nt][1] + b1);
                *(float2*)&C[(size_t)(r0 + 8) * N + c] =
                    make_float2(acc[mt][nt][2] + b0, acc[mt][nt][3] + b1);
            } else {
                uint32_t hi, lo;
                split2h(acc[mt][nt][0], acc[mt][nt][1], hi, lo);
                *(uint32_t*)&Ch[(size_t)r0 * N + c] = hi;
                *(uint32_t*)&Cl[(size_t)r0 * N + c] = lo;
                split2h(acc[mt][nt][2], acc[mt][nt][3], hi, lo);
                *(uint32_t*)&Ch[(size_t)(r0 + 8) * N + c] = hi;
                *(uint32_t*)&Cl[(size_t)(r0 + 8) * N + c] = lo;
            }
        }
    }
}

// ---------------------------------------------------------------------------
// Tensor-core windowed MQA flash attention (64 q rows, 128 thr, 3 CTAs/SM).
// S 3-product fp16; PV single product; output fp16.
// ---------------------------------------------------------------------------
#define AROWB 144
#define ATN_ARR   (64 * AROWB)
#define ATN_SQH   0
#define ATN_SQL   ATN_ARR
#define ATN_STG   (2 * ATN_ARR)
#define ATN_STGSZ (3 * ATN_ARR)       // Kh | Kl | Vh
#define ATN_SMEM  (ATN_STG + 2 * ATN_STGSZ)   // 73728 B -> 3 CTAs/SM

__global__ __launch_bounds__(128, 3)
void attn_mma() {
    extern __shared__ char smc[];
    uint32_t sb = smem_u32(smc);
    const int qt = blockIdx.x, h = blockIdx.y, b = blockIdx.z;
    const int tid = threadIdx.x, lane = tid & 31, w = tid >> 5;
    const int g = lane >> 2, qd = lane & 3;
    const int r8 = lane & 7;

    {
        const char* srcH = (const char*)g_Qh + (size_t)(b * SEQ + qt * 64) * 2304 + h * 128;
        const char* srcL = (const char*)g_Ql + (size_t)(b * SEQ + qt * 64) * 2304 + h * 128;
#pragma unroll
        for (int j = 0; j < 4; j++) {
            int lin = j * 128 + tid, row = lin >> 3, ch = lin & 7;
            CP_ASYNC16(sb + ATN_SQH + row * AROWB + ch * 16,
                       srcH + (size_t)row * 2304 + ch * 16);
            CP_ASYNC16(sb + ATN_SQL + row * AROWB + ch * 16,
                       srcL + (size_t)row * 2304 + ch * 16);
        }
    }

    auto load_kv = [&](int s, int kt) {
        size_t kb = (size_t)(b * SEQ + kt * 64) * 2304;
        uint32_t st = sb + ATN_STG + s * ATN_STGSZ;
#pragma unroll
        for (int j = 0; j < 12; j++) {
            int arr = j >> 2, lin = (j & 3) * 128 + tid;
            int row = lin >> 3, ch = lin & 7;
            const char* base = (arr == 0) ? (const char*)g_Qh + 2048
                             : (arr == 1) ? (const char*)g_Ql + 2048
                                          : (const char*)g_Qh + 2176;
            CP_ASYNC16(st + arr * ATN_ARR + row * AROWB + ch * 16,
                       base + kb + (size_t)row * 2304 + ch * 16);
        }
    };

    int ktlo = qt - 4; if (ktlo < 0) ktlo = 0;
    int kthi = qt + 4; if (kthi > SEQ / 64 - 1) kthi = SEQ / 64 - 1;

    load_kv(0, ktlo); CP_COMMIT();
    if (ktlo < kthi) { load_kv(1, ktlo + 1); CP_COMMIT(); }

    uint32_t qh[4][4], ql[4][4];
    float oacc[8][4];
#pragma unroll
    for (int i = 0; i < 8; i++)
#pragma unroll
        for (int j = 0; j < 4; j++) oacc[i][j] = 0.f;
    float m0 = -1e30f, m1 = -1e30f, l0 = 0.f, l1 = 0.f;

    for (int kt = ktlo; kt <= kthi; kt++) {
        int s = (kt - ktlo) & 1;
        if (kt < kthi) CP_WAIT1(); else CP_WAIT0();
        __syncthreads();

        if (kt == ktlo) {
#pragma unroll
            for (int ks = 0; ks < 4; ks++) {
                uint32_t off = (uint32_t)((w * 16 + (lane & 15)) * AROWB +
                                          ks * 32 + (lane >> 4) * 16);
                LDSM_X4(qh[ks][0], qh[ks][1], qh[ks][2], qh[ks][3], sb + ATN_SQH + off);
                LDSM_X4(ql[ks][0], ql[ks][1], ql[ks][2], ql[ks][3], sb + ATN_SQL + off);
            }
        }

        uint32_t stg = sb + ATN_STG + s * ATN_STGSZ;
        uint32_t pKh = stg, pKl = stg + ATN_ARR;
        uint32_t pVh = stg + 2 * ATN_ARR;

        float sacc[8][4];
#pragma unroll
        for (int i = 0; i < 8; i++)
#pragma unroll
            for (int j = 0; j < 4; j++) sacc[i][j] = 0.f;

#pragma unroll
        for (int ks = 0; ks < 4; ks++)
#pragma unroll
            for (int sg = 0; sg < 4; sg++) {
                uint32_t off = (uint32_t)((sg * 16 + ((lane >> 4) & 1) * 8 + r8) * AROWB +
                                          ks * 32 + ((lane >> 3) & 1) * 16);
                uint32_t kh0, kh1, kh2, kh3, kl0, kl1, kl2, kl3;
                LDSM_X4(kh0, kh1, kh2, kh3, pKh + off);
                LDSM_X4(kl0, kl1, kl2, kl3, pKl + off);
                mma16816(sacc[sg * 2],     qh[ks], kh0, kh1);
                mma16816(sacc[sg * 2],     qh[ks], kl0, kl1);
                mma16816(sacc[sg * 2],     ql[ks], kh0, kh1);
                mma16816(sacc[sg * 2 + 1], qh[ks], kh2, kh3);
                mma16816(sacc[sg * 2 + 1], qh[ks], kl2, kl3);
                mma16816(sacc[sg * 2 + 1], ql[ks], kh2, kh3);
            }

        int rel = kt - qt;
#pragma unroll
        for (int nt = 0; nt < 8; nt++)
#pragma unroll
            for (int e = 0; e < 4; e++) sacc[nt][e] *= 0.125f;
        if (rel == 4 || rel == -4) {
#pragma unroll
            for (int nt = 0; nt < 8; nt++)
#pragma unroll
                for (int e = 0; e < 4; e++) {
                    int ri = w * 16 + g + ((e >= 2) ? 8 : 0);
                    int cj = nt * 8 + 2 * qd + (e & 1);
                    bool ok = (rel == 4) ? (cj <= ri) : (cj >= ri);
                    if (!ok) sacc[nt][e] = -1e30f;
                }
        }

        float rm0 = -1e30f, rm1 = -1e30f;
#pragma unroll
        for (int nt = 0; nt < 8; nt++) {
            rm0 = fmaxf(rm0, fmaxf(sacc[nt][0], sacc[nt][1]));
            rm1 = fmaxf(rm1, fmaxf(sacc[nt][2], sacc[nt][3]));
        }
        rm0 = fmaxf(rm0, __shfl_xor_sync(0xffffffffu, rm0, 1));
        rm0 = fmaxf(rm0, __shfl_xor_sync(0xffffffffu, rm0, 2));
        rm1 = fmaxf(rm1, __shfl_xor_sync(0xffffffffu, rm1, 1));
        rm1 = fmaxf(rm1, __shfl_xor_sync(0xffffffffu, rm1, 2));
        float nm0 = fmaxf(m0, rm0), nm1 = fmaxf(m1, rm1);
        float c0 = __expf(m0 - nm0), c1 = __expf(m1 - nm1);
        m0 = nm0; m1 = nm1;

        float sum0 = 0.f, sum1 = 0.f;
#pragma unroll
        for (int nt = 0; nt < 8; nt++) {
            sacc[nt][0] = __expf(sacc[nt][0] - nm0);
            sacc[nt][1] = __expf(sacc[nt][1] - nm0);
            sacc[nt][2] = __expf(sacc[nt][2] - nm1);
            sacc[nt][3] = __expf(sacc[nt][3] - nm1);
            sum0 += sacc[nt][0] + sacc[nt][1];
            sum1 += sacc[nt][2] + sacc[nt][3];
        }
        sum0 += __shfl_xor_sync(0xffffffffu, sum0, 1);
        sum0 += __shfl_xor_sync(0xffffffffu, sum0, 2);
        sum1 += __shfl_xor_sync(0xffffffffu, sum1, 1);
        sum1 += __shfl_xor_sync(0xffffffffu, sum1, 2);
        l0 = l0 * c0 + sum0; l1 = l1 * c1 + sum1;
#pragma unroll
        for (int nt = 0; nt < 8; nt++) {
            oacc[nt][0] *= c0; oacc[nt][1] *= c0;
            oacc[nt][2] *= c1; oacc[nt][3] *= c1;
        }

        uint32_t ph[4][4];
#pragma unroll
        for (int kg = 0; kg < 4; kg++) {
            ph[kg][0] = pack2h(sacc[2 * kg][0],     sacc[2 * kg][1]);
            ph[kg][1] = pack2h(sacc[2 * kg][2],     sacc[2 * kg][3]);
            ph[kg][2] = pack2h(sacc[2 * kg + 1][0], sacc[2 * kg + 1][1]);
            ph[kg][3] = pack2h(sacc[2 * kg + 1][2], sacc[2 * kg + 1][3]);
        }

#pragma unroll
        for (int kg = 0; kg < 4; kg++)
#pragma unroll
            for (int dg = 0; dg < 4; dg++) {
                uint32_t off = (uint32_t)((kg * 16 + ((lane >> 3) & 1) * 8 + r8) * AROWB +
                                          dg * 32 + ((lane >> 4) & 1) * 16);
                uint32_t vh0, vh1, vh2, vh3;
                LDSM_X4T(vh0, vh1, vh2, vh3, pVh + off);
                mma16816(oacc[dg * 2],     ph[kg], vh0, vh1);
                mma16816(oacc[dg * 2 + 1], ph[kg], vh2, vh3);
            }

        __syncthreads();
        if (kt + 2 <= kthi) { load_kv(s, kt + 2); CP_COMMIT(); }
    }

    float inv0 = 1.0f / l0, inv1 = 1.0f / l1;
    size_t row0 = (size_t)(b * SEQ + qt * 64 + w * 16 + g);
    size_t row1 = row0 + 8;
#pragma unroll
    for (int nt = 0; nt < 8; nt++) {
        int col = h * 64 + nt * 8 + 2 * qd;
        *(uint32_t*)&g_Oh[row0 * WIDTH + col] =
            pack2h(oacc[nt][0] * inv0, oacc[nt][1] * inv0);
        *(uint32_t*)&g_Oh[row1 * WIDTH + col] =
            pack2h(oacc[nt][2] * inv1, oacc[nt][3] * inv1);
    }
}

// ---------------------------------------------------------------------------
// Launch
// ---------------------------------------------------------------------------
extern "C" void kernel_launch(void* const* d_in, const int* in_sizes, int n_in,
                              void* d_out, int out_size) {
    const float* x  = (const float*)d_in[0];
    const float* Wq = (const float*)d_in[1];
    const float* Wk = (const float*)d_in[2];
    const float* Wv = (const float*)d_in[3];
    const float* Wf = (const float*)d_in[4];
    const float* bf = (const float*)d_in[5];
    float* out = (float*)d_out;
    (void)in_sizes; (void)n_in; (void)out_size;

    __half *pAh, *pWh, *pFh, *pQh, *pQl, *pOh;
    cudaGetSymbolAddress((void**)&pAh, g_Ah);
    cudaGetSymbolAddress((void**)&pWh, g_Wh);
    cudaGetSymbolAddress((void**)&pFh, g_Fh);
    cudaGetSymbolAddress((void**)&pQh, g_Qh);
    cudaGetSymbolAddress((void**)&pQl, g_Ql);
    cudaGetSymbolAddress((void**)&pOh, g_Oh);

    cudaFuncSetAttribute(mmagemm,
                         cudaFuncAttributeMaxDynamicSharedMemorySize, GEMM_SMEM);
    cudaFuncSetAttribute(attn_mma,
                         cudaFuncAttributeMaxDynamicSharedMemorySize, ATN_SMEM);

    // fused conversions (x, packed W, Wf -> fp16)
    convert_all<<<(NALLQ + 255) / 256, 256>>>(x, Wq, Wk, Wv, Wf);

    // QKV projection (single product) -> fp16 hi/lo qkv
    mmagemm<<<dim3(NQKV / 128, TOK / 128), 256, GEMM_SMEM>>>(
        pAh, pWh, nullptr, pQh, pQl, TOK, NQKV, WIDTH, nullptr);

    // tensor-core windowed attention -> fp16 O
    attn_mma<<<dim3(SEQ / 64, NH, BATCH), 128, ATN_SMEM>>>();

    // output projection + bias (single product) -> fp32 out
    mmagemm<<<dim3(WIDTH / 128, TOK / 128), 256, GEMM_SMEM>>>(
        pOh, pFh, out, nullptr, nullptr, TOK, WIDTH, WIDTH, bf);
}

// round 14
// speedup vs baseline: 1.9134x; 1.2195x over previous
#include <cuda_runtime.h>
#include <cuda_fp16.h>
#include <cstdint>
#include <math.h>

// Problem constants
#define SEQ    2048
#define BATCH  2
#define WIDTH  1024
#define NH     16
#define HD     64
#define WIN    256
#define TOK    (BATCH*SEQ)     // 4096
#define NQKV   1152            // 1024 q + 64 k + 64 v

// ---------------------------------------------------------------------------
// Scratch (device globals).  Everything fp16 single-precision-compensated
// only through fp32 accumulators; all GEMMs single fp16 product.
// ---------------------------------------------------------------------------
__device__ __half g_Ah[TOK * WIDTH];                         // x fp16
__device__ __half g_Wh[NQKV * WIDTH];                        // [Wq;Wk;Wv] fp16
__device__ __half g_Fh[WIDTH * WIDTH];                       // Wf fp16
__device__ __half g_Qh[TOK * NQKV];                          // qkv fp16
__device__ __half g_Oh[TOK * WIDTH];                         // attn out fp16

// ---------------------------------------------------------------------------
// Helpers
// ---------------------------------------------------------------------------
__device__ __forceinline__ uint32_t smem_u32(const void* p) {
    uint32_t a;
    asm("{ .reg .u64 t; cvta.to.shared.u64 t, %1; cvt.u32.u64 %0, t; }"
        : "=r"(a) : "l"(p));
    return a;
}

#define CP_ASYNC16(sa, ga) \
    asm volatile("cp.async.cg.shared.global [%0], [%1], 16;" :: "r"(sa), "l"(ga))
#define CP_COMMIT() asm volatile("cp.async.commit_group;" ::: "memory")
#define CP_WAIT1()  asm volatile("cp.async.wait_group 1;" ::: "memory")
#define CP_WAIT0()  asm volatile("cp.async.wait_group 0;" ::: "memory")

#define LDSM_X4(r0, r1, r2, r3, addr) \
    asm volatile("ldmatrix.sync.aligned.m8n8.x4.shared.b16 {%0,%1,%2,%3}, [%4];" \
        : "=r"(r0), "=r"(r1), "=r"(r2), "=r"(r3) : "r"(addr))
#define LDSM_X4T(r0, r1, r2, r3, addr) \
    asm volatile("ldmatrix.sync.aligned.m8n8.x4.trans.shared.b16 {%0,%1,%2,%3}, [%4];" \
        : "=r"(r0), "=r"(r1), "=r"(r2), "=r"(r3) : "r"(addr))

__device__ __forceinline__ void mma16816(float* c, const uint32_t* a,
                                         uint32_t b0, uint32_t b1) {
    asm volatile(
        "mma.sync.aligned.m16n8k16.row.col.f32.f16.f16.f32 "
        "{%0,%1,%2,%3}, {%4,%5,%6,%7}, {%8,%9}, {%0,%1,%2,%3};"
        : "+f"(c[0]), "+f"(c[1]), "+f"(c[2]), "+f"(c[3])
        : "r"(a[0]), "r"(a[1]), "r"(a[2]), "r"(a[3]), "r"(b0), "r"(b1));
}

__device__ __forceinline__ uint32_t packh(__half a, __half b) {
    __half2 t; t.x = a; t.y = b;
    return *(uint32_t*)&t;
}
__device__ __forceinline__ uint32_t pack2h(float a, float b) {
    return packh(__float2half_rn(a), __float2half_rn(b));
}

// ---------------------------------------------------------------------------
// One fused conversion kernel: x -> Ah ; [Wq;Wk;Wv] -> Wh ; Wf -> Fh.
// ---------------------------------------------------------------------------
#define NXQ (TOK * WIDTH / 4)
#define NWQ (NQKV * WIDTH / 4)
#define NFQ (WIDTH * WIDTH / 4)
#define NALLQ (NXQ + NWQ + NFQ)

__global__ void convert_all(const float* __restrict__ x,
                            const float* __restrict__ Wq,
                            const float* __restrict__ Wk,
                            const float* __restrict__ Wv,
                            const float* __restrict__ Wf) {
    int q = blockIdx.x * blockDim.x + threadIdx.x;
    if (q < NXQ) {
        int i = q * 4;
        float4 v = *(const float4*)(x + i);
        __half2* H = (__half2*)(g_Ah + i);
        H[0] = __half2(__float2half_rn(v.x), __float2half_rn(v.y));
        H[1] = __half2(__float2half_rn(v.z), __float2half_rn(v.w));
    } else if (q < NXQ + NWQ) {
        int e = (q - NXQ) * 4;
        int row = e >> 10, c = e & 1023;
        const float* src;
        if (row < 1024)      src = Wq + (size_t)row * WIDTH + c;
        else if (row < 1088) src = Wk + (size_t)(row - 1024) * WIDTH + c;
        else                 src = Wv + (size_t)(row - 1088) * WIDTH + c;
        float4 v = *(const float4*)src;
        __half2* H = (__half2*)(g_Wh + e);
        H[0] = __half2(__float2half_rn(v.x), __float2half_rn(v.y));
        H[1] = __half2(__float2half_rn(v.z), __float2half_rn(v.w));
    } else if (q < NALLQ) {
        int i = (q - NXQ - NWQ) * 4;
        float4 v = *(const float4*)(Wf + i);
        __half2* H = (__half2*)(g_Fh + i);
        H[0] = __half2(__float2half_rn(v.x), __float2half_rn(v.y));
        H[1] = __half2(__float2half_rn(v.z), __float2half_rn(v.w));
    }
}

// ---------------------------------------------------------------------------
// mma.sync GEMM: C = A @ B^T (+bias), single fp16 product.
// 128x128x32 tile, 8 warps as 4(M)x2(N), 3-stage cp.async, single barrier,
// 2 CTAs/SM.  Output: fp32 (C) or fp16 (Ch).
// ---------------------------------------------------------------------------
#define BK 32
#define ROWB 80
#define ARR_B (128 * ROWB)            // 10240 B
#define STAGE_B (2 * ARR_B)           // Ah | Bh = 20480 B
#define GEMM_SMEM (3 * STAGE_B)       // 61440 B -> 2 CTAs/SM

__global__ __launch_bounds__(256, 2)
void mmagemm(const __half* __restrict__ Ah, const __half* __restrict__ Bh,
             float* __restrict__ C, __half* __restrict__ Ch,
             int M, int N, int K, const float* __restrict__ bias) {
    extern __shared__ char smem[];
    uint32_t sb = smem_u32(smem);
    const int tid  = threadIdx.x;
    const int lane = tid & 31;
    const int wid  = tid >> 5;
    const int wm   = wid & 3;
    const int wn   = wid >> 2;
    const int m0 = blockIdx.y * 128;
    const int n0 = blockIdx.x * 128;
    const int NK = K / BK;
    const size_t RS = (size_t)K * 2;

    const int crow = tid >> 1;
    const int ccol = (tid & 1) * 2;
    const uint32_t s_off0 = crow * ROWB + ccol * 16;
    const char* gA0 = (const char*)Ah + (size_t)(m0 + crow) * RS + ccol * 16;
    const char* gB0 = (const char*)Bh + (size_t)(n0 + crow) * RS + ccol * 16;

    auto load_stage = [&](int s, int it) {
        uint32_t st = sb + s * STAGE_B;
        size_t kb = (size_t)it * (BK * 2);
        CP_ASYNC16(st + 0 * ARR_B + s_off0,      gA0 + kb);
        CP_ASYNC16(st + 0 * ARR_B + s_off0 + 16, gA0 + kb + 16);
        CP_ASYNC16(st + 1 * ARR_B + s_off0,      gB0 + kb);
        CP_ASYNC16(st + 1 * ARR_B + s_off0 + 16, gB0 + kb + 16);
    };

    float acc[2][8][4];
#pragma unroll
    for (int i = 0; i < 2; i++)
#pragma unroll
        for (int j = 0; j < 8; j++)
#pragma unroll
            for (int q = 0; q < 4; q++) acc[i][j][q] = 0.f;

    const int asub = lane >> 3;
    const int a_row_in = (lane & 7) + 8 * (asub & 1);
    const int a_chunk  = asub >> 1;
    const int b_row_in = (lane & 7) + 8 * (asub >> 1);
    const int b_chunk  = asub & 1;

    load_stage(0, 0); CP_COMMIT();
    load_stage(1, 1); CP_COMMIT();

    for (int it = 0; it < NK; ++it) {
        if (it + 1 < NK) CP_WAIT1(); else CP_WAIT0();
        __syncthreads();
        if (it + 2 < NK) { load_stage((it + 2) % 3, it + 2); CP_COMMIT(); }

        uint32_t st  = sb + (it % 3) * STAGE_B;
        uint32_t pAh = st;
        uint32_t pBh = st + ARR_B;

#pragma unroll
        for (int kk = 0; kk < 2; kk++) {
            uint32_t ah[2][4], bh[4][4];
#pragma unroll
            for (int mt = 0; mt < 2; mt++) {
                uint32_t off = (uint32_t)((wm * 32 + mt * 16 + a_row_in) * ROWB +
                                          (kk * 2 + a_chunk) * 16);
                LDSM_X4(ah[mt][0], ah[mt][1], ah[mt][2], ah[mt][3], pAh + off);
            }
#pragma unroll
            for (int p = 0; p < 4; p++) {
                uint32_t off = (uint32_t)((wn * 64 + p * 16 + b_row_in) * ROWB +
                                          (kk * 2 + b_chunk) * 16);
                LDSM_X4(bh[p][0], bh[p][1], bh[p][2], bh[p][3], pBh + off);
            }
#pragma unroll
            for (int mt = 0; mt < 2; mt++)
#pragma unroll
                for (int p = 0; p < 4; p++)
#pragma unroll
                    for (int hh = 0; hh < 2; hh++)
                        mma16816(acc[mt][p * 2 + hh], ah[mt],
                                 bh[p][hh * 2], bh[p][hh * 2 + 1]);
        }
    }

    const int gid = lane >> 2;
    const int qid = lane & 3;
#pragma unroll
    for (int mt = 0; mt < 2; mt++) {
        int r0 = m0 + wm * 32 + mt * 16 + gid;
#pragma unroll
        for (int nt = 0; nt < 8; nt++) {
            int c = n0 + wn * 64 + nt * 8 + qid * 2;
            if (C) {
                float b0 = 0.f, b1 = 0.f;
                if (bias) { b0 = bias[c]; b1 = bias[c + 1]; }
                *(float2*)&C[(size_t)r0 * N + c] =
                    make_float2(acc[mt][nt][0] + b0, acc[mt][nt][1] + b1);
                *(float2*)&C[(size_t)(r0 + 8) * N + c] =
                    make_float2(acc[mt][nt][2] + b0, acc[mt][nt][3] + b1);
            } else {
                *(uint32_t*)&Ch[(size_t)r0 * N + c] =
                    pack2h(acc[mt][nt][0], acc[mt][nt][1]);
                *(uint32_t*)&Ch[(size_t)(r0 + 8) * N + c] =
                    pack2h(acc[mt][nt][2], acc[mt][nt][3]);
            }
        }
    }
}

// ---------------------------------------------------------------------------
// Tensor-core windowed MQA flash attention (64 q rows, 128 thr, 4 CTAs/SM).
// S single product fp16; PV single product; output fp16.
// ---------------------------------------------------------------------------
#define AROWB 144
#define ATN_ARR   (64 * AROWB)        // 9216 B
#define ATN_SQ    0
#define ATN_STG   ATN_ARR
#define ATN_STGSZ (2 * ATN_ARR)       // Kh | Vh
#define ATN_SMEM  (ATN_ARR + 2 * ATN_STGSZ)   // 46080 B -> 4 CTAs/SM

__global__ __launch_bounds__(128, 4)
void attn_mma() {
    extern __shared__ char smc[];
    uint32_t sb = smem_u32(smc);
    const int qt = blockIdx.x, h = blockIdx.y, b = blockIdx.z;
    const int tid = threadIdx.x, lane = tid & 31, w = tid >> 5;
    const int g = lane >> 2, qd = lane & 3;
    const int r8 = lane & 7;

    // ---- async-load Q tile (fp16) ----
    {
        const char* srcH = (const char*)g_Qh + (size_t)(b * SEQ + qt * 64) * 2304 + h * 128;
#pragma unroll
        for (int j = 0; j < 4; j++) {
            int lin = j * 128 + tid, row = lin >> 3, ch = lin & 7;
            CP_ASYNC16(sb + ATN_SQ + row * AROWB + ch * 16,
                       srcH + (size_t)row * 2304 + ch * 16);
        }
    }

    auto load_kv = [&](int s, int kt) {
        size_t kb = (size_t)(b * SEQ + kt * 64) * 2304;
        uint32_t st = sb + ATN_STG + s * ATN_STGSZ;
#pragma unroll
        for (int j = 0; j < 8; j++) {
            int arr = j >> 2, lin = (j & 3) * 128 + tid;
            int row = lin >> 3, ch = lin & 7;
            const char* base = (arr == 0) ? (const char*)g_Qh + 2048     // K
                                          : (const char*)g_Qh + 2176;    // V
            CP_ASYNC16(st + arr * ATN_ARR + row * AROWB + ch * 16,
                       base + kb + (size_t)row * 2304 + ch * 16);
        }
    };

    int ktlo = qt - 4; if (ktlo < 0) ktlo = 0;
    int kthi = qt + 4; if (kthi > SEQ / 64 - 1) kthi = SEQ / 64 - 1;

    load_kv(0, ktlo); CP_COMMIT();
    if (ktlo < kthi) { load_kv(1, ktlo + 1); CP_COMMIT(); }

    uint32_t qh[4][4];
    float oacc[8][4];
#pragma unroll
    for (int i = 0; i < 8; i++)
#pragma unroll
        for (int j = 0; j < 4; j++) oacc[i][j] = 0.f;
    float m0 = -1e30f, m1 = -1e30f, l0 = 0.f, l1 = 0.f;

    for (int kt = ktlo; kt <= kthi; kt++) {
        int s = (kt - ktlo) & 1;
        if (kt < kthi) CP_WAIT1(); else CP_WAIT0();
        __syncthreads();

        if (kt == ktlo) {
#pragma unroll
            for (int ks = 0; ks < 4; ks++) {
                uint32_t off = (uint32_t)((w * 16 + (lane & 15)) * AROWB +
                                          ks * 32 + (lane >> 4) * 16);
                LDSM_X4(qh[ks][0], qh[ks][1], qh[ks][2], qh[ks][3], sb + ATN_SQ + off);
            }
        }

        uint32_t stg = sb + ATN_STG + s * ATN_STGSZ;
        uint32_t pKh = stg;
        uint32_t pVh = stg + ATN_ARR;

        // ---- S = Q @ K^T (single product) ----
        float sacc[8][4];
#pragma unroll
        for (int i = 0; i < 8; i++)
#pragma unroll
            for (int j = 0; j < 4; j++) sacc[i][j] = 0.f;

#pragma unroll
        for (int ks = 0; ks < 4; ks++)
#pragma unroll
            for (int sg = 0; sg < 4; sg++) {
                uint32_t off = (uint32_t)((sg * 16 + ((lane >> 4) & 1) * 8 + r8) * AROWB +
                                          ks * 32 + ((lane >> 3) & 1) * 16);
                uint32_t kh0, kh1, kh2, kh3;
                LDSM_X4(kh0, kh1, kh2, kh3, pKh + off);
                mma16816(sacc[sg * 2],     qh[ks], kh0, kh1);
                mma16816(sacc[sg * 2 + 1], qh[ks], kh2, kh3);
            }

        int rel = kt - qt;
#pragma unroll
        for (int nt = 0; nt < 8; nt++)
#pragma unroll
            for (int e = 0; e < 4; e++) sacc[nt][e] *= 0.125f;
        if (rel == 4 || rel == -4) {
#pragma unroll
            for (int nt = 0; nt < 8; nt++)
#pragma unroll
                for (int e = 0; e < 4; e++) {
                    int ri = w * 16 + g + ((e >= 2) ? 8 : 0);
                    int cj = nt * 8 + 2 * qd + (e & 1);
                    bool ok = (rel == 4) ? (cj <= ri) : (cj >= ri);
                    if (!ok) sacc[nt][e] = -1e30f;
                }
        }

        float rm0 = -1e30f, rm1 = -1e30f;
#pragma unroll
        for (int nt = 0; nt < 8; nt++) {
            rm0 = fmaxf(rm0, fmaxf(sacc[nt][0], sacc[nt][1]));
            rm1 = fmaxf(rm1, fmaxf(sacc[nt][2], sacc[nt][3]));
        }
        rm0 = fmaxf(rm0, __shfl_xor_sync(0xffffffffu, rm0, 1));
        rm0 = fmaxf(rm0, __shfl_xor_sync(0xffffffffu, rm0, 2));
        rm1 = fmaxf(rm1, __shfl_xor_sync(0xffffffffu, rm1, 1));
        rm1 = fmaxf(rm1, __shfl_xor_sync(0xffffffffu, rm1, 2));
        float nm0 = fmaxf(m0, rm0), nm1 = fmaxf(m1, rm1);
        float c0 = __expf(m0 - nm0), c1 = __expf(m1 - nm1);
        m0 = nm0; m1 = nm1;

        float sum0 = 0.f, sum1 = 0.f;
#pragma unroll
        for (int nt = 0; nt < 8; nt++) {
            sacc[nt][0] = __expf(sacc[nt][0] - nm0);
            sacc[nt][1] = __expf(sacc[nt][1] - nm0);
            sacc[nt][2] = __expf(sacc[nt][2] - nm1);
            sacc[nt][3] = __expf(sacc[nt][3] - nm1);
            sum0 += sacc[nt][0] + sacc[nt][1];
            sum1 += sacc[nt][2] + sacc[nt][3];
        }
        sum0 += __shfl_xor_sync(0xffffffffu, sum0, 1);
        sum0 += __shfl_xor_sync(0xffffffffu, sum0, 2);
        sum1 += __shfl_xor_sync(0xffffffffu, sum1, 1);
        sum1 += __shfl_xor_sync(0xffffffffu, sum1, 2);
        l0 = l0 * c0 + sum0; l1 = l1 * c1 + sum1;
#pragma unroll
        for (int nt = 0; nt < 8; nt++) {
            oacc[nt][0] *= c0; oacc[nt][1] *= c0;
            oacc[nt][2] *= c1; oacc[nt][3] *= c1;
        }

        // ---- P frags (fp16) ----
        uint32_t ph[4][4];
#pragma unroll
        for (int kg = 0; kg < 4; kg++) {
            ph[kg][0] = pack2h(sacc[2 * kg][0],     sacc[2 * kg][1]);
            ph[kg][1] = pack2h(sacc[2 * kg][2],     sacc[2 * kg][3]);
            ph[kg][2] = pack2h(sacc[2 * kg + 1][0], sacc[2 * kg + 1][1]);
            ph[kg][3] = pack2h(sacc[2 * kg + 1][2], sacc[2 * kg + 1][3]);
        }

        // ---- O += P @ V (single product) ----
#pragma unroll
        for (int kg = 0; kg < 4; kg++)
#pragma unroll
            for (int dg = 0; dg < 4; dg++) {
                uint32_t off = (uint32_t)((kg * 16 + ((lane >> 3) & 1) * 8 + r8) * AROWB +
                                          dg * 32 + ((lane >> 4) & 1) * 16);
                uint32_t vh0, vh1, vh2, vh3;
                LDSM_X4T(vh0, vh1, vh2, vh3, pVh + off);
                mma16816(oacc[dg * 2],     ph[kg], vh0, vh1);
                mma16816(oacc[dg * 2 + 1], ph[kg], vh2, vh3);
            }

        __syncthreads();
        if (kt + 2 <= kthi) { load_kv(s, kt + 2); CP_COMMIT(); }
    }

    float inv0 = 1.0f / l0, inv1 = 1.0f / l1;
    size_t row0 = (size_t)(b * SEQ + qt * 64 + w * 16 + g);
    size_t row1 = row0 + 8;
#pragma unroll
    for (int nt = 0; nt < 8; nt++) {
        int col = h * 64 + nt * 8 + 2 * qd;
        *(uint32_t*)&g_Oh[row0 * WIDTH + col] =
            pack2h(oacc[nt][0] * inv0, oacc[nt][1] * inv0);
        *(uint32_t*)&g_Oh[row1 * WIDTH + col] =
            pack2h(oacc[nt][2] * inv1, oacc[nt][3] * inv1);
    }
}

// ---------------------------------------------------------------------------
// Launch
// ---------------------------------------------------------------------------
extern "C" void kernel_launch(void* const* d_in, const int* in_sizes, int n_in,
                              void* d_out, int out_size) {
    const float* x  = (const float*)d_in[0];
    const float* Wq = (const float*)d_in[1];
    const float* Wk = (const float*)d_in[2];
    const float* Wv = (const float*)d_in[3];
    const float* Wf = (const float*)d_in[4];
    const float* bf = (const float*)d_in[5];
    float* out = (float*)d_out;
    (void)in_sizes; (void)n_in; (void)out_size;

    __half *pAh, *pWh, *pFh, *pQh, *pOh;
    cudaGetSymbolAddress((void**)&pAh, g_Ah);
    cudaGetSymbolAddress((void**)&pWh, g_Wh);
    cudaGetSymbolAddress((void**)&pFh, g_Fh);
    cudaGetSymbolAddress((void**)&pQh, g_Qh);
    cudaGetSymbolAddress((void**)&pOh, g_Oh);

    cudaFuncSetAttribute(mmagemm,
                         cudaFuncAttributeMaxDynamicSharedMemorySize, GEMM_SMEM);
    cudaFuncSetAttribute(attn_mma,
                         cudaFuncAttributeMaxDynamicSharedMemorySize, ATN_SMEM);

    // fused conversions (x, packed W, Wf -> fp16)
    convert_all<<<(NALLQ + 255) / 256, 256>>>(x, Wq, Wk, Wv, Wf);

    // QKV projection -> fp16 qkv
    mmagemm<<<dim3(NQKV / 128, TOK / 128), 256, GEMM_SMEM>>>(
        pAh, pWh, nullptr, pQh, TOK, NQKV, WIDTH, nullptr);

    // tensor-core windowed attention -> fp16 O
    attn_mma<<<dim3(SEQ / 64, NH, BATCH), 128, ATN_SMEM>>>();

    // output projection + bias -> fp32 out
    mmagemm<<<dim3(WIDTH / 128, TOK / 128), 256, GEMM_SMEM>>>(
        pOh, pFh, out, nullptr, TOK, WIDTH, WIDTH, bf);
}